// round 2
// baseline (speedup 1.0000x reference)
#include <cuda_runtime.h>
#include <math.h>

// Problem constants
#define BB   2
#define TT   2048
#define EMB  2048
#define NH   16
#define DH   128          // head dim
#define QKV3 (3 * EMB)    // 6144

// Scratch (no cudaMalloc allowed) — device globals.
__device__ float g_qkv[BB * TT * QKV3];   // [B,T,3C]  ~100.7 MB
__device__ float g_y  [BB * TT * EMB];    // [B,T,C]   ~33.5 MB

// ---------------------------------------------------------------------------
// SGEMM: C[M,N] = A[M,K] @ B[K,N], row-major, all dims multiples of 128/8.
// BM=BN=128, BK=8, TM=TN=8, 256 threads.
// ---------------------------------------------------------------------------
__global__ __launch_bounds__(256)
void sgemm128(int M, int N, int K,
              const float* __restrict__ A,
              const float* __restrict__ B,
              float* __restrict__ C)
{
    constexpr int BM = 128, BN = 128, BK = 8, TM = 8, TN = 8;
    __shared__ float As[BK][BM];
    __shared__ float Bs[BK][BN];

    const int tid = threadIdx.x;
    const int threadCol = tid % (BN / TN);   // 0..15
    const int threadRow = tid / (BN / TN);   // 0..15

    A += (size_t)blockIdx.y * BM * K;
    B += (size_t)blockIdx.x * BN;
    C += (size_t)blockIdx.y * BM * N + blockIdx.x * BN;

    const int innerRowA = tid / (BK / 4);        // tid/2 -> 0..127
    const int innerColA = (tid % (BK / 4)) * 4;  // 0 or 4
    const int innerRowB = tid / (BN / 4);        // tid/32 -> 0..7
    const int innerColB = (tid % (BN / 4)) * 4;  // 0..124

    float acc[TM][TN];
    #pragma unroll
    for (int i = 0; i < TM; i++)
        #pragma unroll
        for (int j = 0; j < TN; j++)
            acc[i][j] = 0.0f;

    float regM[TM], regN[TN];

    for (int k0 = 0; k0 < K; k0 += BK) {
        float4 a = *(const float4*)(A + (size_t)innerRowA * K + innerColA);
        As[innerColA + 0][innerRowA] = a.x;
        As[innerColA + 1][innerRowA] = a.y;
        As[innerColA + 2][innerRowA] = a.z;
        As[innerColA + 3][innerRowA] = a.w;
        *(float4*)(&Bs[innerRowB][innerColB]) =
            *(const float4*)(B + (size_t)innerRowB * N + innerColB);
        __syncthreads();
        A += BK;
        B += (size_t)BK * N;

        #pragma unroll
        for (int k = 0; k < BK; k++) {
            #pragma unroll
            for (int i = 0; i < TM; i++) regM[i] = As[k][threadRow * TM + i];
            #pragma unroll
            for (int j = 0; j < TN; j++) regN[j] = Bs[k][threadCol * TN + j];
            #pragma unroll
            for (int i = 0; i < TM; i++)
                #pragma unroll
                for (int j = 0; j < TN; j++)
                    acc[i][j] = fmaf(regM[i], regN[j], acc[i][j]);
        }
        __syncthreads();
    }

    #pragma unroll
    for (int i = 0; i < TM; i++) {
        #pragma unroll
        for (int j = 0; j < TN; j += 4) {
            float4 v = make_float4(acc[i][j], acc[i][j+1], acc[i][j+2], acc[i][j+3]);
            *(float4*)(&C[(size_t)(threadRow * TM + i) * N + threadCol * TN + j]) = v;
        }
    }
}

// ---------------------------------------------------------------------------
// Flash attention (fp32, causal). One block = 64 queries of one (b,h).
// Br = Bc = 64, D = 128, 256 threads.
// Q/K/V tiles in dynamic smem (row stride 129 to dodge bank conflicts).
// grid: (T/64, H, B)
// ---------------------------------------------------------------------------
#define BR 64
#define BC 64
#define QSTRIDE 129
#define SSTRIDE 65

__global__ __launch_bounds__(256)
void flash_attn_kernel(const float* __restrict__ qkv, float* __restrict__ y)
{
    const int qt = blockIdx.x;
    const int h  = blockIdx.y;
    const int b  = blockIdx.z;
    const int q0 = qt * BR;
    const int tid = threadIdx.x;

    extern __shared__ float sm[];
    float* sQ = sm;                    // [64][129]
    float* sK = sQ + BR * QSTRIDE;     // [64][129]
    float* sV = sK + BC * QSTRIDE;     // [64][129]
    float* sS = sV + BC * QSTRIDE;     // [64][65]
    float* sM = sS + BR * SSTRIDE;     // [64]
    float* sL = sM + BR;               // [64]
    float* sAlpha = sL + BR;           // [64]

    const float scale = 0.08838834764831845f;  // 1/sqrt(128)

    // Load Q tile (pre-scaled).
    {
        const float* qbase = qkv + ((size_t)(b * TT + q0)) * QKV3 + h * DH;
        #pragma unroll
        for (int it = 0; it < (BR * DH) / 256; it++) {
            int e = tid + 256 * it;
            int i = e / DH, d = e % DH;
            sQ[i * QSTRIDE + d] = qbase[(size_t)i * QKV3 + d] * scale;
        }
    }
    // Init softmax state.
    if (tid < BR) { sM[tid] = -1e30f; sL[tid] = 0.0f; }

    // Per-thread O accumulators: 4 rows x 8 cols.
    const int oRow0 = (tid / 16) * 4;       // 0..60
    const int oCol0 = (tid % 16) * 8;       // 0..120
    float o[4][8];
    #pragma unroll
    for (int r = 0; r < 4; r++)
        #pragma unroll
        for (int c = 0; c < 8; c++) o[r][c] = 0.0f;

    // S micro-tile mapping: 4 rows x 4 cols per thread.
    const int sRow0 = (tid / 16) * 4;
    const int sCol0 = (tid % 16) * 4;

    __syncthreads();

    for (int kt = 0; kt <= qt; kt++) {
        const int k0 = kt * BC;
        // Load K and V tiles.
        {
            const float* kbase = qkv + ((size_t)(b * TT + k0)) * QKV3 + EMB + h * DH;
            const float* vbase = qkv + ((size_t)(b * TT + k0)) * QKV3 + 2 * EMB + h * DH;
            #pragma unroll
            for (int it = 0; it < (BC * DH) / 256; it++) {
                int e = tid + 256 * it;
                int j = e / DH, d = e % DH;
                sK[j * QSTRIDE + d] = kbase[(size_t)j * QKV3 + d];
                sV[j * QSTRIDE + d] = vbase[(size_t)j * QKV3 + d];
            }
        }
        __syncthreads();

        // S = Q @ K^T (4x4 per thread).
        {
            float accS[4][4];
            #pragma unroll
            for (int r = 0; r < 4; r++)
                #pragma unroll
                for (int c = 0; c < 4; c++) accS[r][c] = 0.0f;
            for (int kk = 0; kk < DH; kk++) {
                float qv[4], kv[4];
                #pragma unroll
                for (int r = 0; r < 4; r++) qv[r] = sQ[(sRow0 + r) * QSTRIDE + kk];
                #pragma unroll
                for (int c = 0; c < 4; c++) kv[c] = sK[(sCol0 + c) * QSTRIDE + kk];
                #pragma unroll
                for (int r = 0; r < 4; r++)
                    #pragma unroll
                    for (int c = 0; c < 4; c++)
                        accS[r][c] = fmaf(qv[r], kv[c], accS[r][c]);
            }
            // causal mask + store
            #pragma unroll
            for (int r = 0; r < 4; r++) {
                int qi = q0 + sRow0 + r;
                #pragma unroll
                for (int c = 0; c < 4; c++) {
                    int kj = k0 + sCol0 + c;
                    sS[(sRow0 + r) * SSTRIDE + sCol0 + c] =
                        (kj <= qi) ? accS[r][c] : -1e30f;
                }
            }
        }
        __syncthreads();

        // Online softmax, one thread per row.
        if (tid < BR) {
            const int i = tid;
            float m_old = sM[i];
            float m_new = m_old;
            #pragma unroll 8
            for (int j = 0; j < BC; j++)
                m_new = fmaxf(m_new, sS[i * SSTRIDE + j]);
            float alpha = __expf(m_old - m_new);
            float rsum = 0.0f;
            #pragma unroll 8
            for (int j = 0; j < BC; j++) {
                float p = __expf(sS[i * SSTRIDE + j] - m_new);
                sS[i * SSTRIDE + j] = p;
                rsum += p;
            }
            sM[i] = m_new;
            sL[i] = sL[i] * alpha + rsum;
            sAlpha[i] = alpha;
        }
        __syncthreads();

        // O = O*alpha + P @ V  (4x8 per thread).
        {
            #pragma unroll
            for (int r = 0; r < 4; r++) {
                float a = sAlpha[oRow0 + r];
                #pragma unroll
                for (int c = 0; c < 8; c++) o[r][c] *= a;
            }
            for (int j = 0; j < BC; j++) {
                float pv[4], vv[8];
                #pragma unroll
                for (int r = 0; r < 4; r++) pv[r] = sS[(oRow0 + r) * SSTRIDE + j];
                #pragma unroll
                for (int c = 0; c < 8; c++) vv[c] = sV[j * QSTRIDE + oCol0 + c];
                #pragma unroll
                for (int r = 0; r < 4; r++)
                    #pragma unroll
                    for (int c = 0; c < 8; c++)
                        o[r][c] = fmaf(pv[r], vv[c], o[r][c]);
            }
        }
        __syncthreads();
    }

    // Epilogue: normalize by l, write to y[b, q, h*128 + d].
    #pragma unroll
    for (int r = 0; r < 4; r++) {
        float inv = 1.0f / sL[oRow0 + r];
        float* ybase = y + ((size_t)(b * TT + q0 + oRow0 + r)) * EMB + h * DH + oCol0;
        #pragma unroll
        for (int c = 0; c < 8; c++)
            ybase[c] = o[r][c] * inv;
    }
}

// ---------------------------------------------------------------------------
// Launch
// ---------------------------------------------------------------------------
extern "C" void kernel_launch(void* const* d_in, const int* in_sizes, int n_in,
                              void* d_out, int out_size)
{
    const float* x      = (const float*)d_in[0];   // [B,T,C]
    const float* W_attn = (const float*)d_in[1];   // [C, 3C]
    const float* W_proj = (const float*)d_in[2];   // [C, C]
    float* out = (float*)d_out;                    // [B,T,C]

    float *qkv, *y;
    cudaGetSymbolAddress((void**)&qkv, g_qkv);
    cudaGetSymbolAddress((void**)&y, g_y);

    const int M = BB * TT;   // 4096

    // 1) QKV projection: [4096,2048] @ [2048,6144]
    {
        dim3 grid(QKV3 / 128, M / 128);
        sgemm128<<<grid, 256>>>(M, QKV3, EMB, x, W_attn, qkv);
    }

    // 2) Flash attention
    {
        const int smem = (3 * BR * QSTRIDE + BR * SSTRIDE + 3 * BR) * (int)sizeof(float);
        cudaFuncSetAttribute(flash_attn_kernel,
                             cudaFuncAttributeMaxDynamicSharedMemorySize, smem);
        dim3 grid(TT / BR, NH, BB);
        flash_attn_kernel<<<grid, 256, smem>>>(qkv, y);
    }

    // 3) Output projection: [4096,2048] @ [2048,2048]
    {
        dim3 grid(EMB / 128, M / 128);
        sgemm128<<<grid, 256>>>(M, EMB, EMB, y, W_proj, out);
    }
}

// round 4
// speedup vs baseline: 1.7710x; 1.7710x over previous
#include <cuda_runtime.h>
#include <math.h>

// Problem constants
#define BB   2
#define TT   2048
#define EMB  2048
#define NH   16
#define DH   128
#define QKV3 (3 * EMB)    // 6144

// Scratch — device globals (no cudaMalloc allowed).
__device__ float g_qkv[BB * TT * QKV3];   // [B,T,3C]
__device__ float g_y  [BB * TT * EMB];    // [B,T,C]

// ---------------------------------------------------------------------------
// tf32 helpers
// ---------------------------------------------------------------------------
__device__ __forceinline__ unsigned f2tf32(float f) {
    unsigned r;
    asm volatile("cvt.rna.tf32.f32 %0, %1;" : "=r"(r) : "f"(f));
    return r;
}

__device__ __forceinline__ void mma_tf32(float* c, const unsigned* a, const unsigned* b) {
    asm volatile(
        "mma.sync.aligned.m16n8k8.row.col.f32.tf32.tf32.f32 "
        "{%0,%1,%2,%3}, {%4,%5,%6,%7}, {%8,%9}, {%0,%1,%2,%3};"
        : "+f"(c[0]), "+f"(c[1]), "+f"(c[2]), "+f"(c[3])
        : "r"(a[0]), "r"(a[1]), "r"(a[2]), "r"(a[3]),
          "r"(b[0]), "r"(b[1]));
}

#define CP_ASYNC16(dst, src) \
    asm volatile("cp.async.cg.shared.global [%0], [%1], 16;\n" :: "r"(dst), "l"(src))
#define CP_COMMIT() asm volatile("cp.async.commit_group;\n" ::)
#define CP_WAIT(n)  asm volatile("cp.async.wait_group %0;\n" :: "n"(n))

// ---------------------------------------------------------------------------
// tf32 tensor-core GEMM: C[M,N] = A[M,K] @ B[K,N], row-major.
// BM=BN=128, BK=32, 256 threads (8 warps: 2x4 warp grid, warp tile 64x32).
// cp.async double-buffered. Strides chosen for conflict-free fragment LDS:
//   As[m][k] stride 36  -> addr%32 = 4*(lane/4)+lane%4 (32 distinct)
//   Bs[k][n] stride 136 -> addr%32 = 8*(lane%4)+lane/4 (32 distinct)
// ---------------------------------------------------------------------------
#define GBM 128
#define GBN 128
#define GBK 32
#define ASTR 36
#define BSTR 136
#define A_STAGE (GBM * ASTR)          // 4608 floats
#define B_STAGE (GBK * BSTR)          // 4352 floats
#define STAGE_FLOATS (A_STAGE + B_STAGE)

__global__ __launch_bounds__(256)
void gemm_tf32(int M, int N, int K,
               const float* __restrict__ A,
               const float* __restrict__ B,
               float* __restrict__ C)
{
    extern __shared__ float sm[];
    float* sA[2] = { sm, sm + STAGE_FLOATS };
    float* sB[2] = { sm + A_STAGE, sm + STAGE_FLOATS + A_STAGE };

    const int tid  = threadIdx.x;
    const int lane = tid & 31;
    const int warp = tid >> 5;
    const int warpM = warp & 1;        // 0..1
    const int warpN = warp >> 1;       // 0..3
    const int mBase = warpM * 64;
    const int nBase = warpN * 32;

    const size_t blockRowOff = (size_t)blockIdx.y * GBM;
    const size_t blockColOff = (size_t)blockIdx.x * GBN;

    // load mapping
    const int aRow  = tid >> 3;          // 0..31 (stride 32, 4 iters)
    const int aCol4 = (tid & 7) * 4;     // 0..28
    const int bRow  = tid >> 5;          // 0..7 (stride 8, 4 iters)
    const int bCol4 = (tid & 31) * 4;    // 0..124

    const int numTiles = K / GBK;

    auto issue_tile = [&](int t, int stage) {
        const float* Ag = A + (blockRowOff) * K + (size_t)t * GBK;
        const float* Bg = B + ((size_t)t * GBK) * N + blockColOff;
        unsigned sa = (unsigned)__cvta_generic_to_shared(sA[stage]);
        unsigned sb = (unsigned)__cvta_generic_to_shared(sB[stage]);
        #pragma unroll
        for (int i = 0; i < 4; i++) {
            int r = aRow + i * 32;
            CP_ASYNC16(sa + (r * ASTR + aCol4) * 4,
                       Ag + (size_t)r * K + aCol4);
        }
        #pragma unroll
        for (int i = 0; i < 4; i++) {
            int r = bRow + i * 8;
            CP_ASYNC16(sb + (r * BSTR + bCol4) * 4,
                       Bg + (size_t)r * N + bCol4);
        }
        CP_COMMIT();
    };

    float acc[4][4][4];
    #pragma unroll
    for (int i = 0; i < 4; i++)
        #pragma unroll
        for (int j = 0; j < 4; j++)
            #pragma unroll
            for (int r = 0; r < 4; r++) acc[i][j][r] = 0.0f;

    issue_tile(0, 0);

    for (int t = 0; t < numTiles; t++) {
        const int stage = t & 1;
        if (t + 1 < numTiles) {
            issue_tile(t + 1, (t + 1) & 1);
            CP_WAIT(1);
        } else {
            CP_WAIT(0);
        }
        __syncthreads();

        const float* As = sA[stage];
        const float* Bs = sB[stage];

        #pragma unroll
        for (int kk = 0; kk < GBK; kk += 8) {
            unsigned afr[4][4], bfr[4][2];
            #pragma unroll
            for (int mt = 0; mt < 4; mt++) {
                int m0 = mBase + mt * 16 + (lane >> 2);
                int k0 = kk + (lane & 3);
                afr[mt][0] = f2tf32(As[(m0    ) * ASTR + k0    ]);
                afr[mt][1] = f2tf32(As[(m0 + 8) * ASTR + k0    ]);
                afr[mt][2] = f2tf32(As[(m0    ) * ASTR + k0 + 4]);
                afr[mt][3] = f2tf32(As[(m0 + 8) * ASTR + k0 + 4]);
            }
            #pragma unroll
            for (int nt = 0; nt < 4; nt++) {
                int n0 = nBase + nt * 8 + (lane >> 2);
                int k0 = kk + (lane & 3);
                bfr[nt][0] = f2tf32(Bs[(k0    ) * BSTR + n0]);
                bfr[nt][1] = f2tf32(Bs[(k0 + 4) * BSTR + n0]);
            }
            #pragma unroll
            for (int mt = 0; mt < 4; mt++)
                #pragma unroll
                for (int nt = 0; nt < 4; nt++)
                    mma_tf32(acc[mt][nt], afr[mt], bfr[nt]);
        }
        __syncthreads();
    }

    // Epilogue: c0/c1 at (row, 2*tig), c2/c3 at (row+8, 2*tig)
    float* Cb = C + (blockRowOff) * N + blockColOff;
    #pragma unroll
    for (int mt = 0; mt < 4; mt++) {
        #pragma unroll
        for (int nt = 0; nt < 4; nt++) {
            int row = mBase + mt * 16 + (lane >> 2);
            int col = nBase + nt * 8 + (lane & 3) * 2;
            *(float2*)(Cb + (size_t)row * N + col) =
                make_float2(acc[mt][nt][0], acc[mt][nt][1]);
            *(float2*)(Cb + (size_t)(row + 8) * N + col) =
                make_float2(acc[mt][nt][2], acc[mt][nt][3]);
        }
    }
}

// ---------------------------------------------------------------------------
// Flash attention (fp32, causal) — unchanged from passing baseline.
// ---------------------------------------------------------------------------
#define BR 64
#define BC 64
#define QSTRIDE 129
#define SSTRIDE 65

__global__ __launch_bounds__(256)
void flash_attn_kernel(const float* __restrict__ qkv, float* __restrict__ y)
{
    const int qt = blockIdx.x;
    const int h  = blockIdx.y;
    const int b  = blockIdx.z;
    const int q0 = qt * BR;
    const int tid = threadIdx.x;

    extern __shared__ float sm[];
    float* sQ = sm;
    float* sK = sQ + BR * QSTRIDE;
    float* sV = sK + BC * QSTRIDE;
    float* sS = sV + BC * QSTRIDE;
    float* sM = sS + BR * SSTRIDE;
    float* sL = sM + BR;
    float* sAlpha = sL + BR;

    const float scale = 0.08838834764831845f;

    {
        const float* qbase = qkv + ((size_t)(b * TT + q0)) * QKV3 + h * DH;
        #pragma unroll
        for (int it = 0; it < (BR * DH) / 256; it++) {
            int e = tid + 256 * it;
            int i = e / DH, d = e % DH;
            sQ[i * QSTRIDE + d] = qbase[(size_t)i * QKV3 + d] * scale;
        }
    }
    if (tid < BR) { sM[tid] = -1e30f; sL[tid] = 0.0f; }

    const int oRow0 = (tid / 16) * 4;
    const int oCol0 = (tid % 16) * 8;
    float o[4][8];
    #pragma unroll
    for (int r = 0; r < 4; r++)
        #pragma unroll
        for (int c = 0; c < 8; c++) o[r][c] = 0.0f;

    const int sRow0 = (tid / 16) * 4;
    const int sCol0 = (tid % 16) * 4;

    __syncthreads();

    for (int kt = 0; kt <= qt; kt++) {
        const int k0 = kt * BC;
        {
            const float* kbase = qkv + ((size_t)(b * TT + k0)) * QKV3 + EMB + h * DH;
            const float* vbase = qkv + ((size_t)(b * TT + k0)) * QKV3 + 2 * EMB + h * DH;
            #pragma unroll
            for (int it = 0; it < (BC * DH) / 256; it++) {
                int e = tid + 256 * it;
                int j = e / DH, d = e % DH;
                sK[j * QSTRIDE + d] = kbase[(size_t)j * QKV3 + d];
                sV[j * QSTRIDE + d] = vbase[(size_t)j * QKV3 + d];
            }
        }
        __syncthreads();

        {
            float accS[4][4];
            #pragma unroll
            for (int r = 0; r < 4; r++)
                #pragma unroll
                for (int c = 0; c < 4; c++) accS[r][c] = 0.0f;
            for (int kk = 0; kk < DH; kk++) {
                float qv[4], kv[4];
                #pragma unroll
                for (int r = 0; r < 4; r++) qv[r] = sQ[(sRow0 + r) * QSTRIDE + kk];
                #pragma unroll
                for (int c = 0; c < 4; c++) kv[c] = sK[(sCol0 + c) * QSTRIDE + kk];
                #pragma unroll
                for (int r = 0; r < 4; r++)
                    #pragma unroll
                    for (int c = 0; c < 4; c++)
                        accS[r][c] = fmaf(qv[r], kv[c], accS[r][c]);
            }
            #pragma unroll
            for (int r = 0; r < 4; r++) {
                int qi = q0 + sRow0 + r;
                #pragma unroll
                for (int c = 0; c < 4; c++) {
                    int kj = k0 + sCol0 + c;
                    sS[(sRow0 + r) * SSTRIDE + sCol0 + c] =
                        (kj <= qi) ? accS[r][c] : -1e30f;
                }
            }
        }
        __syncthreads();

        if (tid < BR) {
            const int i = tid;
            float m_old = sM[i];
            float m_new = m_old;
            #pragma unroll 8
            for (int j = 0; j < BC; j++)
                m_new = fmaxf(m_new, sS[i * SSTRIDE + j]);
            float alpha = __expf(m_old - m_new);
            float rsum = 0.0f;
            #pragma unroll 8
            for (int j = 0; j < BC; j++) {
                float p = __expf(sS[i * SSTRIDE + j] - m_new);
                sS[i * SSTRIDE + j] = p;
                rsum += p;
            }
            sM[i] = m_new;
            sL[i] = sL[i] * alpha + rsum;
            sAlpha[i] = alpha;
        }
        __syncthreads();

        {
            #pragma unroll
            for (int r = 0; r < 4; r++) {
                float a = sAlpha[oRow0 + r];
                #pragma unroll
                for (int c = 0; c < 8; c++) o[r][c] *= a;
            }
            for (int j = 0; j < BC; j++) {
                float pv[4], vv[8];
                #pragma unroll
                for (int r = 0; r < 4; r++) pv[r] = sS[(oRow0 + r) * SSTRIDE + j];
                #pragma unroll
                for (int c = 0; c < 8; c++) vv[c] = sV[j * QSTRIDE + oCol0 + c];
                #pragma unroll
                for (int r = 0; r < 4; r++)
                    #pragma unroll
                    for (int c = 0; c < 8; c++)
                        o[r][c] = fmaf(pv[r], vv[c], o[r][c]);
            }
        }
        __syncthreads();
    }

    #pragma unroll
    for (int r = 0; r < 4; r++) {
        float inv = 1.0f / sL[oRow0 + r];
        float* ybase = y + ((size_t)(b * TT + q0 + oRow0 + r)) * EMB + h * DH + oCol0;
        #pragma unroll
        for (int c = 0; c < 8; c++)
            ybase[c] = o[r][c] * inv;
    }
}

// ---------------------------------------------------------------------------
// Launch
// ---------------------------------------------------------------------------
extern "C" void kernel_launch(void* const* d_in, const int* in_sizes, int n_in,
                              void* d_out, int out_size)
{
    const float* x      = (const float*)d_in[0];
    const float* W_attn = (const float*)d_in[1];
    const float* W_proj = (const float*)d_in[2];
    float* out = (float*)d_out;

    float *qkv, *y;
    cudaGetSymbolAddress((void**)&qkv, g_qkv);
    cudaGetSymbolAddress((void**)&y, g_y);

    const int M = BB * TT;   // 4096
    const int gemmSmem = 2 * STAGE_FLOATS * (int)sizeof(float);  // 71680 B
    cudaFuncSetAttribute(gemm_tf32,
                         cudaFuncAttributeMaxDynamicSharedMemorySize, gemmSmem);

    // 1) QKV projection: [4096,2048] @ [2048,6144]
    {
        dim3 grid(QKV3 / GBN, M / GBM);
        gemm_tf32<<<grid, 256, gemmSmem>>>(M, QKV3, EMB, x, W_attn, qkv);
    }

    // 2) Flash attention
    {
        const int smem = (3 * BR * QSTRIDE + BR * SSTRIDE + 3 * BR) * (int)sizeof(float);
        cudaFuncSetAttribute(flash_attn_kernel,
                             cudaFuncAttributeMaxDynamicSharedMemorySize, smem);
        dim3 grid(TT / BR, NH, BB);
        flash_attn_kernel<<<grid, 256, smem>>>(qkv, y);
    }

    // 3) Output projection: [4096,2048] @ [2048,2048]
    {
        dim3 grid(EMB / GBN, M / GBM);
        gemm_tf32<<<grid, 256, gemmSmem>>>(M, EMB, EMB, y, W_proj, out);
    }
}

// round 6
// speedup vs baseline: 3.7071x; 2.0932x over previous
#include <cuda_runtime.h>
#include <math.h>

// Problem constants
#define BB   2
#define TT   2048
#define EMB  2048
#define NH   16
#define DH   128
#define QKV3 (3 * EMB)    // 6144

// Scratch — device globals (no cudaMalloc allowed).
__device__ float g_qkv[BB * TT * QKV3];   // [B,T,3C]
__device__ float g_y  [BB * TT * EMB];    // [B,T,C]

// ---------------------------------------------------------------------------
// tf32 helpers
// ---------------------------------------------------------------------------
__device__ __forceinline__ unsigned f2tf32(float f) {
    unsigned r;
    asm volatile("cvt.rna.tf32.f32 %0, %1;" : "=r"(r) : "f"(f));
    return r;
}

__device__ __forceinline__ void mma_tf32(float* c, const unsigned* a, const unsigned* b) {
    asm volatile(
        "mma.sync.aligned.m16n8k8.row.col.f32.tf32.tf32.f32 "
        "{%0,%1,%2,%3}, {%4,%5,%6,%7}, {%8,%9}, {%0,%1,%2,%3};"
        : "+f"(c[0]), "+f"(c[1]), "+f"(c[2]), "+f"(c[3])
        : "r"(a[0]), "r"(a[1]), "r"(a[2]), "r"(a[3]),
          "r"(b[0]), "r"(b[1]));
}

#define CP_ASYNC16(dst, src) \
    asm volatile("cp.async.cg.shared.global [%0], [%1], 16;\n" :: "r"(dst), "l"(src))
#define CP_COMMIT() asm volatile("cp.async.commit_group;\n" ::)
#define CP_WAIT(n)  asm volatile("cp.async.wait_group %0;\n" :: "n"(n))

// ---------------------------------------------------------------------------
// tf32 tensor-core GEMM (unchanged from R4 passing kernel)
// ---------------------------------------------------------------------------
#define GBM 128
#define GBN 128
#define GBK 32
#define ASTR 36
#define BSTR 136
#define A_STAGE (GBM * ASTR)
#define B_STAGE (GBK * BSTR)
#define STAGE_FLOATS (A_STAGE + B_STAGE)

__global__ __launch_bounds__(256)
void gemm_tf32(int M, int N, int K,
               const float* __restrict__ A,
               const float* __restrict__ B,
               float* __restrict__ C)
{
    extern __shared__ float sm[];
    float* sA[2] = { sm, sm + STAGE_FLOATS };
    float* sB[2] = { sm + A_STAGE, sm + STAGE_FLOATS + A_STAGE };

    const int tid  = threadIdx.x;
    const int lane = tid & 31;
    const int warp = tid >> 5;
    const int warpM = warp & 1;
    const int warpN = warp >> 1;
    const int mBase = warpM * 64;
    const int nBase = warpN * 32;

    const size_t blockRowOff = (size_t)blockIdx.y * GBM;
    const size_t blockColOff = (size_t)blockIdx.x * GBN;

    const int aRow  = tid >> 3;
    const int aCol4 = (tid & 7) * 4;
    const int bRow  = tid >> 5;
    const int bCol4 = (tid & 31) * 4;

    const int numTiles = K / GBK;

    auto issue_tile = [&](int t, int stage) {
        const float* Ag = A + (blockRowOff) * K + (size_t)t * GBK;
        const float* Bg = B + ((size_t)t * GBK) * N + blockColOff;
        unsigned sa = (unsigned)__cvta_generic_to_shared(sA[stage]);
        unsigned sb = (unsigned)__cvta_generic_to_shared(sB[stage]);
        #pragma unroll
        for (int i = 0; i < 4; i++) {
            int r = aRow + i * 32;
            CP_ASYNC16(sa + (r * ASTR + aCol4) * 4,
                       Ag + (size_t)r * K + aCol4);
        }
        #pragma unroll
        for (int i = 0; i < 4; i++) {
            int r = bRow + i * 8;
            CP_ASYNC16(sb + (r * BSTR + bCol4) * 4,
                       Bg + (size_t)r * N + bCol4);
        }
        CP_COMMIT();
    };

    float acc[4][4][4];
    #pragma unroll
    for (int i = 0; i < 4; i++)
        #pragma unroll
        for (int j = 0; j < 4; j++)
            #pragma unroll
            for (int r = 0; r < 4; r++) acc[i][j][r] = 0.0f;

    issue_tile(0, 0);

    for (int t = 0; t < numTiles; t++) {
        const int stage = t & 1;
        if (t + 1 < numTiles) {
            issue_tile(t + 1, (t + 1) & 1);
            CP_WAIT(1);
        } else {
            CP_WAIT(0);
        }
        __syncthreads();

        const float* As = sA[stage];
        const float* Bs = sB[stage];

        #pragma unroll
        for (int kk = 0; kk < GBK; kk += 8) {
            unsigned afr[4][4], bfr[4][2];
            #pragma unroll
            for (int mt = 0; mt < 4; mt++) {
                int m0 = mBase + mt * 16 + (lane >> 2);
                int k0 = kk + (lane & 3);
                afr[mt][0] = f2tf32(As[(m0    ) * ASTR + k0    ]);
                afr[mt][1] = f2tf32(As[(m0 + 8) * ASTR + k0    ]);
                afr[mt][2] = f2tf32(As[(m0    ) * ASTR + k0 + 4]);
                afr[mt][3] = f2tf32(As[(m0 + 8) * ASTR + k0 + 4]);
            }
            #pragma unroll
            for (int nt = 0; nt < 4; nt++) {
                int n0 = nBase + nt * 8 + (lane >> 2);
                int k0 = kk + (lane & 3);
                bfr[nt][0] = f2tf32(Bs[(k0    ) * BSTR + n0]);
                bfr[nt][1] = f2tf32(Bs[(k0 + 4) * BSTR + n0]);
            }
            #pragma unroll
            for (int mt = 0; mt < 4; mt++)
                #pragma unroll
                for (int nt = 0; nt < 4; nt++)
                    mma_tf32(acc[mt][nt], afr[mt], bfr[nt]);
        }
        __syncthreads();
    }

    float* Cb = C + (blockRowOff) * N + blockColOff;
    #pragma unroll
    for (int mt = 0; mt < 4; mt++) {
        #pragma unroll
        for (int nt = 0; nt < 4; nt++) {
            int row = mBase + mt * 16 + (lane >> 2);
            int col = nBase + nt * 8 + (lane & 3) * 2;
            *(float2*)(Cb + (size_t)row * N + col) =
                make_float2(acc[mt][nt][0], acc[mt][nt][1]);
            *(float2*)(Cb + (size_t)(row + 8) * N + col) =
                make_float2(acc[mt][nt][2], acc[mt][nt][3]);
        }
    }
}

// ---------------------------------------------------------------------------
// Tensor-core flash attention (tf32 mma, fp32 accum, causal).
// BR=BC=64, 256 threads = 8 warps in a 2x4 grid.
//   S phase:  warp tile 32x16 of S[64x64], K-dim 128 (16 k-steps)
//   PV phase: warp tile 32x32 of O[64x128], K-dim 64 (8 k-steps)
// Conflict-free strides: sQ/sK 132 (bank=4r+k), sV 136 (8k+n), sS 68 (4r+k).
// K/V double-buffered with cp.async (raw fp32; rna-rounded at fragment load).
// ---------------------------------------------------------------------------
#define AQSTR 132
#define AVSTR 136
#define ASSTR 68
#define KV_STAGE_K (64 * AQSTR)
#define KV_STAGE_V (64 * AVSTR)

__global__ __launch_bounds__(256)
void flash_attn_tc(const float* __restrict__ qkv, float* __restrict__ y)
{
    const int qt = blockIdx.x;
    const int h  = blockIdx.y;
    const int b  = blockIdx.z;
    const int q0 = qt * 64;
    const int tid  = threadIdx.x;
    const int lane = tid & 31;
    const int warp = tid >> 5;
    const int warpM = warp & 1;   // 0..1
    const int warpN = warp >> 1;  // 0..3

    extern __shared__ float sm[];
    float* sQ  = sm;                         // 64*132
    float* sK  = sQ + 64 * AQSTR;            // 2 * 64*132
    float* sV  = sK + 2 * KV_STAGE_K;        // 2 * 64*136
    float* sS  = sV + 2 * KV_STAGE_V;        // 64*68
    float* sMx = sS + 64 * ASSTR;            // 64
    float* sL  = sMx + 64;                   // 64
    float* sAl = sL + 64;                    // 64

    const float scale = 0.08838834764831845f;  // 1/sqrt(128)

    // ---- Load Q (scaled, tf32-rounded) ----
    {
        const float* qbase = qkv + ((size_t)(b * TT + q0)) * QKV3 + h * DH;
        #pragma unroll
        for (int i = 0; i < 8; i++) {
            int e = tid + 256 * i;           // 0..2047
            int r = e >> 5, d4 = (e & 31) * 4;
            float4 v = *(const float4*)(qbase + (size_t)r * QKV3 + d4);
            sQ[r * AQSTR + d4 + 0] = __uint_as_float(f2tf32(v.x * scale));
            sQ[r * AQSTR + d4 + 1] = __uint_as_float(f2tf32(v.y * scale));
            sQ[r * AQSTR + d4 + 2] = __uint_as_float(f2tf32(v.z * scale));
            sQ[r * AQSTR + d4 + 3] = __uint_as_float(f2tf32(v.w * scale));
        }
    }
    if (tid < 64) { sMx[tid] = -1e30f; sL[tid] = 0.0f; }

    float oacc[2][4][4];
    #pragma unroll
    for (int mt = 0; mt < 2; mt++)
        #pragma unroll
        for (int nt = 0; nt < 4; nt++)
            #pragma unroll
            for (int r = 0; r < 4; r++) oacc[mt][nt][r] = 0.0f;

    // ---- K/V tile cp.async issue ----
    auto issue_kv = [&](int kt, int stage) {
        const int k0 = kt * 64;
        const float* kbase = qkv + ((size_t)(b * TT + k0)) * QKV3 + EMB + h * DH;
        const float* vbase = qkv + ((size_t)(b * TT + k0)) * QKV3 + 2 * EMB + h * DH;
        unsigned sk = (unsigned)__cvta_generic_to_shared(sK + stage * KV_STAGE_K);
        unsigned sv = (unsigned)__cvta_generic_to_shared(sV + stage * KV_STAGE_V);
        #pragma unroll
        for (int i = 0; i < 8; i++) {
            int e = tid + 256 * i;
            int r = e >> 5, d4 = (e & 31) * 4;
            CP_ASYNC16(sk + (r * AQSTR + d4) * 4, kbase + (size_t)r * QKV3 + d4);
            CP_ASYNC16(sv + (r * AVSTR + d4) * 4, vbase + (size_t)r * QKV3 + d4);
        }
        CP_COMMIT();
    };

    issue_kv(0, 0);
    __syncthreads();   // sQ + sMx/sL visible

    for (int kt = 0; kt <= qt; kt++) {
        const int stage = kt & 1;
        const int k0g = kt * 64;

        if (kt + 1 <= qt) {
            issue_kv(kt + 1, (kt + 1) & 1);
            CP_WAIT(1);
        } else {
            CP_WAIT(0);
        }
        __syncthreads();   // K/V[stage] ready; previous sS consumers done

        // ---- S = Q @ K^T (warp tile 32x16) ----
        {
            const float* Ks = sK + stage * KV_STAGE_K;
            float sacc[2][2][4];
            #pragma unroll
            for (int mt = 0; mt < 2; mt++)
                #pragma unroll
                for (int nt = 0; nt < 2; nt++)
                    #pragma unroll
                    for (int r = 0; r < 4; r++) sacc[mt][nt][r] = 0.0f;

            #pragma unroll
            for (int kk = 0; kk < DH; kk += 8) {
                unsigned afr[2][4], bfr[2][2];
                #pragma unroll
                for (int mt = 0; mt < 2; mt++) {
                    int m0 = warpM * 32 + mt * 16 + (lane >> 2);
                    int k0 = kk + (lane & 3);
                    afr[mt][0] = __float_as_uint(sQ[(m0    ) * AQSTR + k0    ]);
                    afr[mt][1] = __float_as_uint(sQ[(m0 + 8) * AQSTR + k0    ]);
                    afr[mt][2] = __float_as_uint(sQ[(m0    ) * AQSTR + k0 + 4]);
                    afr[mt][3] = __float_as_uint(sQ[(m0 + 8) * AQSTR + k0 + 4]);
                }
                #pragma unroll
                for (int nt = 0; nt < 2; nt++) {
                    int n0 = warpN * 16 + nt * 8 + (lane >> 2);
                    int k0 = kk + (lane & 3);
                    bfr[nt][0] = f2tf32(Ks[n0 * AQSTR + k0    ]);
                    bfr[nt][1] = f2tf32(Ks[n0 * AQSTR + k0 + 4]);
                }
                #pragma unroll
                for (int mt = 0; mt < 2; mt++)
                    #pragma unroll
                    for (int nt = 0; nt < 2; nt++)
                        mma_tf32(sacc[mt][nt], afr[mt], bfr[nt]);
            }

            // Store S to smem (mask on diagonal tile).
            const bool diag = (kt == qt);
            #pragma unroll
            for (int mt = 0; mt < 2; mt++) {
                #pragma unroll
                for (int nt = 0; nt < 2; nt++) {
                    int r = warpM * 32 + mt * 16 + (lane >> 2);
                    int c = warpN * 16 + nt * 8 + (lane & 3) * 2;
                    float v0 = sacc[mt][nt][0], v1 = sacc[mt][nt][1];
                    float v2 = sacc[mt][nt][2], v3 = sacc[mt][nt][3];
                    if (diag) {
                        int qi0 = q0 + r, qi1 = q0 + r + 8;
                        int kj0 = k0g + c, kj1 = k0g + c + 1;
                        if (kj0 > qi0) v0 = -1e30f;
                        if (kj1 > qi0) v1 = -1e30f;
                        if (kj0 > qi1) v2 = -1e30f;
                        if (kj1 > qi1) v3 = -1e30f;
                    }
                    *(float2*)(sS + r * ASSTR + c)       = make_float2(v0, v1);
                    *(float2*)(sS + (r + 8) * ASSTR + c) = make_float2(v2, v3);
                }
            }
        }
        __syncthreads();

        // ---- Online softmax: 4 threads/row, strided cols (conflict-free) ----
        {
            const int r = tid >> 2, sub = tid & 3;
            float* row = sS + r * ASSTR;
            float m_old = sMx[r];
            float mx = m_old;
            #pragma unroll
            for (int j = 0; j < 16; j++)
                mx = fmaxf(mx, row[sub + 4 * j]);
            mx = fmaxf(mx, __shfl_xor_sync(0xFFFFFFFFu, mx, 1));
            mx = fmaxf(mx, __shfl_xor_sync(0xFFFFFFFFu, mx, 2));
            float sum = 0.0f;
            #pragma unroll
            for (int j = 0; j < 16; j++) {
                float p = __expf(row[sub + 4 * j] - mx);
                float pr = __uint_as_float(f2tf32(p));
                row[sub + 4 * j] = pr;
                sum += pr;
            }
            sum += __shfl_xor_sync(0xFFFFFFFFu, sum, 1);
            sum += __shfl_xor_sync(0xFFFFFFFFu, sum, 2);
            if (sub == 0) {
                float alpha = __expf(m_old - mx);
                sAl[r] = alpha;
                sMx[r] = mx;
                sL[r]  = sL[r] * alpha + sum;
            }
        }
        __syncthreads();

        // ---- O = O*alpha + P @ V (warp tile 32x32) ----
        {
            const float* Vs = sV + stage * KV_STAGE_V;
            #pragma unroll
            for (int mt = 0; mt < 2; mt++) {
                int r0 = warpM * 32 + mt * 16 + (lane >> 2);
                float a0 = sAl[r0], a1 = sAl[r0 + 8];
                #pragma unroll
                for (int nt = 0; nt < 4; nt++) {
                    oacc[mt][nt][0] *= a0;
                    oacc[mt][nt][1] *= a0;
                    oacc[mt][nt][2] *= a1;
                    oacc[mt][nt][3] *= a1;
                }
            }
            #pragma unroll
            for (int kk = 0; kk < 64; kk += 8) {
                unsigned pfr[2][4], vfr[4][2];
                #pragma unroll
                for (int mt = 0; mt < 2; mt++) {
                    int m0 = warpM * 32 + mt * 16 + (lane >> 2);
                    int k0 = kk + (lane & 3);
                    pfr[mt][0] = __float_as_uint(sS[(m0    ) * ASSTR + k0    ]);
                    pfr[mt][1] = __float_as_uint(sS[(m0 + 8) * ASSTR + k0    ]);
                    pfr[mt][2] = __float_as_uint(sS[(m0    ) * ASSTR + k0 + 4]);
                    pfr[mt][3] = __float_as_uint(sS[(m0 + 8) * ASSTR + k0 + 4]);
                }
                #pragma unroll
                for (int nt = 0; nt < 4; nt++) {
                    int n0 = warpN * 32 + nt * 8 + (lane >> 2);
                    int k0 = kk + (lane & 3);
                    vfr[nt][0] = f2tf32(Vs[(k0    ) * AVSTR + n0]);
                    vfr[nt][1] = f2tf32(Vs[(k0 + 4) * AVSTR + n0]);
                }
                #pragma unroll
                for (int mt = 0; mt < 2; mt++)
                    #pragma unroll
                    for (int nt = 0; nt < 4; nt++)
                        mma_tf32(oacc[mt][nt], pfr[mt], vfr[nt]);
            }
        }
        __syncthreads();   // protect sS and K/V stage for next iteration
    }

    // ---- Epilogue: normalize and write y[b, q, h*128 + d] ----
    #pragma unroll
    for (int mt = 0; mt < 2; mt++) {
        int r = warpM * 32 + mt * 16 + (lane >> 2);
        float inv0 = 1.0f / sL[r];
        float inv1 = 1.0f / sL[r + 8];
        #pragma unroll
        for (int nt = 0; nt < 4; nt++) {
            int c = warpN * 32 + nt * 8 + (lane & 3) * 2;
            float* y0 = y + ((size_t)(b * TT + q0 + r)) * EMB + h * DH + c;
            float* y1 = y + ((size_t)(b * TT + q0 + r + 8)) * EMB + h * DH + c;
            *(float2*)y0 = make_float2(oacc[mt][nt][0] * inv0, oacc[mt][nt][1] * inv0);
            *(float2*)y1 = make_float2(oacc[mt][nt][2] * inv1, oacc[mt][nt][3] * inv1);
        }
    }
}

// ---------------------------------------------------------------------------
// Launch
// ---------------------------------------------------------------------------
extern "C" void kernel_launch(void* const* d_in, const int* in_sizes, int n_in,
                              void* d_out, int out_size)
{
    const float* x      = (const float*)d_in[0];
    const float* W_attn = (const float*)d_in[1];
    const float* W_proj = (const float*)d_in[2];
    float* out = (float*)d_out;

    float *qkv, *y;
    cudaGetSymbolAddress((void**)&qkv, g_qkv);
    cudaGetSymbolAddress((void**)&y, g_y);

    const int M = BB * TT;   // 4096
    const int gemmSmem = 2 * STAGE_FLOATS * (int)sizeof(float);  // 71680 B
    cudaFuncSetAttribute(gemm_tf32,
                         cudaFuncAttributeMaxDynamicSharedMemorySize, gemmSmem);

    // 1) QKV projection: [4096,2048] @ [2048,6144]
    {
        dim3 grid(QKV3 / GBN, M / GBM);
        gemm_tf32<<<grid, 256, gemmSmem>>>(M, QKV3, EMB, x, W_attn, qkv);
    }

    // 2) Flash attention (tensor core)
    {
        const int attnSmem = (64 * AQSTR + 2 * KV_STAGE_K + 2 * KV_STAGE_V +
                              64 * ASSTR + 3 * 64) * (int)sizeof(float); // 189184 B
        cudaFuncSetAttribute(flash_attn_tc,
                             cudaFuncAttributeMaxDynamicSharedMemorySize, attnSmem);
        dim3 grid(TT / 64, NH, BB);
        flash_attn_tc<<<grid, 256, attnSmem>>>(qkv, y);
    }

    // 3) Output projection: [4096,2048] @ [2048,2048]
    {
        dim3 grid(EMB / GBN, M / GBM);
        gemm_tf32<<<grid, 256, gemmSmem>>>(M, EMB, EMB, y, W_proj, out);
    }
}

// round 8
// speedup vs baseline: 3.7999x; 1.0250x over previous
#include <cuda_runtime.h>
#include <math.h>
#include <stdint.h>

// Problem constants
#define BB   2
#define TT   2048
#define EMB  2048
#define NH   16
#define DH   128
#define QKV3 (3 * EMB)    // 6144

// Scratch — device globals (no cudaMalloc allowed).
__device__ float g_qkv[BB * TT * QKV3];   // [B,T,3C] (tf32-valued)
__device__ float g_y  [BB * TT * EMB];    // [B,T,C]  (tf32-valued)
__device__ float g_xr [BB * TT * EMB];    // tf32-rounded x
__device__ float g_w1r[EMB * QKV3];       // tf32-rounded W_attn [K,N]
__device__ float g_w2r[EMB * EMB];        // tf32-rounded W_proj [K,N]

// ---------------------------------------------------------------------------
// helpers
// ---------------------------------------------------------------------------
__device__ __forceinline__ unsigned f2tf32(float f) {
    unsigned r;
    asm volatile("cvt.rna.tf32.f32 %0, %1;" : "=r"(r) : "f"(f));
    return r;
}
__device__ __forceinline__ float rnd_tf32(float f) { return __uint_as_float(f2tf32(f)); }

__device__ __forceinline__ void mma_tf32(float* c, const unsigned* a, const unsigned* b) {
    asm volatile(
        "mma.sync.aligned.m16n8k8.row.col.f32.tf32.tf32.f32 "
        "{%0,%1,%2,%3}, {%4,%5,%6,%7}, {%8,%9}, {%0,%1,%2,%3};"
        : "+f"(c[0]), "+f"(c[1]), "+f"(c[2]), "+f"(c[3])
        : "r"(a[0]), "r"(a[1]), "r"(a[2]), "r"(a[3]),
          "r"(b[0]), "r"(b[1]));
}

#define CP_ASYNC16(dst, src) \
    asm volatile("cp.async.cg.shared.global [%0], [%1], 16;\n" :: "r"(dst), "l"(src))
#define CP_COMMIT() asm volatile("cp.async.commit_group;\n" ::)
#define CP_WAIT(n)  asm volatile("cp.async.wait_group %0;\n" :: "n"(n))

// ---------------------------------------------------------------------------
// Prologue: tf32-round a float4 array.
// ---------------------------------------------------------------------------
__global__ void round_copy4(const float4* __restrict__ src, float4* __restrict__ dst, int n4)
{
    int i = blockIdx.x * blockDim.x + threadIdx.x;
    if (i < n4) {
        float4 v = src[i];
        v.x = rnd_tf32(v.x); v.y = rnd_tf32(v.y);
        v.z = rnd_tf32(v.z); v.w = rnd_tf32(v.w);
        dst[i] = v;
    }
}

// ---------------------------------------------------------------------------
// tf32 tensor-core GEMM: C[M,N] = A[M,K] @ B[K,N], row-major.
// Inputs MUST be tf32-valued fp32 (pre-rounded) — fragment loads are bare LDS.
// BM=BN=128, BK=32, 256 threads (8 warps: 2x4 grid, warp tile 64x32).
// cp.async double-buffered. ROUND: tf32-round C on store (feeds next mma).
// ---------------------------------------------------------------------------
#define GBM 128
#define GBN 128
#define GBK 32
#define ASTR 36
#define BSTR 136
#define A_STAGE (GBM * ASTR)
#define B_STAGE (GBK * BSTR)
#define STAGE_FLOATS (A_STAGE + B_STAGE)

template<bool ROUND>
__global__ __launch_bounds__(256)
void gemm_tf32(int M, int N, int K,
               const float* __restrict__ A,
               const float* __restrict__ B,
               float* __restrict__ C)
{
    extern __shared__ float sm[];
    float* sA[2] = { sm, sm + STAGE_FLOATS };
    float* sB[2] = { sm + A_STAGE, sm + STAGE_FLOATS + A_STAGE };

    const int tid  = threadIdx.x;
    const int lane = tid & 31;
    const int warp = tid >> 5;
    const int warpM = warp & 1;
    const int warpN = warp >> 1;
    const int mBase = warpM * 64;
    const int nBase = warpN * 32;

    const size_t blockRowOff = (size_t)blockIdx.y * GBM;
    const size_t blockColOff = (size_t)blockIdx.x * GBN;

    const int aRow  = tid >> 3;
    const int aCol4 = (tid & 7) * 4;
    const int bRow  = tid >> 5;
    const int bCol4 = (tid & 31) * 4;

    const int numTiles = K / GBK;

    auto issue_tile = [&](int t, int stage) {
        const float* Ag = A + (blockRowOff) * K + (size_t)t * GBK;
        const float* Bg = B + ((size_t)t * GBK) * N + blockColOff;
        unsigned sa = (unsigned)__cvta_generic_to_shared(sA[stage]);
        unsigned sb = (unsigned)__cvta_generic_to_shared(sB[stage]);
        #pragma unroll
        for (int i = 0; i < 4; i++) {
            int r = aRow + i * 32;
            CP_ASYNC16(sa + (r * ASTR + aCol4) * 4,
                       Ag + (size_t)r * K + aCol4);
        }
        #pragma unroll
        for (int i = 0; i < 4; i++) {
            int r = bRow + i * 8;
            CP_ASYNC16(sb + (r * BSTR + bCol4) * 4,
                       Bg + (size_t)r * N + bCol4);
        }
        CP_COMMIT();
    };

    float acc[4][4][4];
    #pragma unroll
    for (int i = 0; i < 4; i++)
        #pragma unroll
        for (int j = 0; j < 4; j++)
            #pragma unroll
            for (int r = 0; r < 4; r++) acc[i][j][r] = 0.0f;

    issue_tile(0, 0);

    for (int t = 0; t < numTiles; t++) {
        const int stage = t & 1;
        if (t + 1 < numTiles) {
            issue_tile(t + 1, (t + 1) & 1);
            CP_WAIT(1);
        } else {
            CP_WAIT(0);
        }
        __syncthreads();

        const float* As = sA[stage];
        const float* Bs = sB[stage];
        const unsigned* Au = (const unsigned*)As;
        const unsigned* Bu = (const unsigned*)Bs;

        #pragma unroll
        for (int kk = 0; kk < GBK; kk += 8) {
            unsigned afr[4][4], bfr[4][2];
            #pragma unroll
            for (int mt = 0; mt < 4; mt++) {
                int m0 = mBase + mt * 16 + (lane >> 2);
                int k0 = kk + (lane & 3);
                afr[mt][0] = Au[(m0    ) * ASTR + k0    ];
                afr[mt][1] = Au[(m0 + 8) * ASTR + k0    ];
                afr[mt][2] = Au[(m0    ) * ASTR + k0 + 4];
                afr[mt][3] = Au[(m0 + 8) * ASTR + k0 + 4];
            }
            #pragma unroll
            for (int nt = 0; nt < 4; nt++) {
                int n0 = nBase + nt * 8 + (lane >> 2);
                int k0 = kk + (lane & 3);
                bfr[nt][0] = Bu[(k0    ) * BSTR + n0];
                bfr[nt][1] = Bu[(k0 + 4) * BSTR + n0];
            }
            #pragma unroll
            for (int mt = 0; mt < 4; mt++)
                #pragma unroll
                for (int nt = 0; nt < 4; nt++)
                    mma_tf32(acc[mt][nt], afr[mt], bfr[nt]);
        }
        __syncthreads();
    }

    float* Cb = C + (blockRowOff) * N + blockColOff;
    #pragma unroll
    for (int mt = 0; mt < 4; mt++) {
        #pragma unroll
        for (int nt = 0; nt < 4; nt++) {
            int row = mBase + mt * 16 + (lane >> 2);
            int col = nBase + nt * 8 + (lane & 3) * 2;
            float v0 = acc[mt][nt][0], v1 = acc[mt][nt][1];
            float v2 = acc[mt][nt][2], v3 = acc[mt][nt][3];
            if (ROUND) {
                v0 = rnd_tf32(v0); v1 = rnd_tf32(v1);
                v2 = rnd_tf32(v2); v3 = rnd_tf32(v3);
            }
            *(float2*)(Cb + (size_t)row * N + col)       = make_float2(v0, v1);
            *(float2*)(Cb + (size_t)(row + 8) * N + col) = make_float2(v2, v3);
        }
    }
}

// ---------------------------------------------------------------------------
// Tensor-core flash attention (tf32 mma.sync, fp32 accum, causal).
// qkv is tf32-valued -> all Q/K/V fragment loads are bare LDS (no cvt).
// 1/sqrt(d) scale applied inside softmax (fp32, exact reformulation).
// ---------------------------------------------------------------------------
#define AQSTR 132
#define AVSTR 136
#define ASSTR 68
#define KV_STAGE_K (64 * AQSTR)
#define KV_STAGE_V (64 * AVSTR)

__global__ __launch_bounds__(256)
void flash_attn_tc(const float* __restrict__ qkv, float* __restrict__ y)
{
    const int qt = blockIdx.x;
    const int h  = blockIdx.y;
    const int b  = blockIdx.z;
    const int q0 = qt * 64;
    const int tid  = threadIdx.x;
    const int lane = tid & 31;
    const int warp = tid >> 5;
    const int warpM = warp & 1;
    const int warpN = warp >> 1;

    extern __shared__ float sm[];
    float* sQ  = sm;
    float* sK  = sQ + 64 * AQSTR;
    float* sV  = sK + 2 * KV_STAGE_K;
    float* sS  = sV + 2 * KV_STAGE_V;
    float* sMx = sS + 64 * ASSTR;
    float* sL  = sMx + 64;
    float* sAl = sL + 64;

    const float scale = 0.08838834764831845f;   // applied in softmax

    // ---- Load Q (raw tf32-valued floats, no scaling/rounding) ----
    {
        const float* qbase = qkv + ((size_t)(b * TT + q0)) * QKV3 + h * DH;
        #pragma unroll
        for (int i = 0; i < 8; i++) {
            int e = tid + 256 * i;
            int r = e >> 5, d4 = (e & 31) * 4;
            *(float4*)(sQ + r * AQSTR + d4) =
                *(const float4*)(qbase + (size_t)r * QKV3 + d4);
        }
    }
    if (tid < 64) { sMx[tid] = -1e30f; sL[tid] = 0.0f; }

    float oacc[2][4][4];
    #pragma unroll
    for (int mt = 0; mt < 2; mt++)
        #pragma unroll
        for (int nt = 0; nt < 4; nt++)
            #pragma unroll
            for (int r = 0; r < 4; r++) oacc[mt][nt][r] = 0.0f;

    auto issue_kv = [&](int kt, int stage) {
        const int k0 = kt * 64;
        const float* kbase = qkv + ((size_t)(b * TT + k0)) * QKV3 + EMB + h * DH;
        const float* vbase = qkv + ((size_t)(b * TT + k0)) * QKV3 + 2 * EMB + h * DH;
        unsigned sk = (unsigned)__cvta_generic_to_shared(sK + stage * KV_STAGE_K);
        unsigned sv = (unsigned)__cvta_generic_to_shared(sV + stage * KV_STAGE_V);
        #pragma unroll
        for (int i = 0; i < 8; i++) {
            int e = tid + 256 * i;
            int r = e >> 5, d4 = (e & 31) * 4;
            CP_ASYNC16(sk + (r * AQSTR + d4) * 4, kbase + (size_t)r * QKV3 + d4);
            CP_ASYNC16(sv + (r * AVSTR + d4) * 4, vbase + (size_t)r * QKV3 + d4);
        }
        CP_COMMIT();
    };

    issue_kv(0, 0);
    __syncthreads();

    for (int kt = 0; kt <= qt; kt++) {
        const int stage = kt & 1;
        const int k0g = kt * 64;

        if (kt + 1 <= qt) {
            issue_kv(kt + 1, (kt + 1) & 1);
            CP_WAIT(1);
        } else {
            CP_WAIT(0);
        }
        __syncthreads();

        // ---- S = Q @ K^T (unscaled) ----
        {
            const unsigned* Qu = (const unsigned*)sQ;
            const unsigned* Ku = (const unsigned*)(sK + stage * KV_STAGE_K);
            float sacc[2][2][4];
            #pragma unroll
            for (int mt = 0; mt < 2; mt++)
                #pragma unroll
                for (int nt = 0; nt < 2; nt++)
                    #pragma unroll
                    for (int r = 0; r < 4; r++) sacc[mt][nt][r] = 0.0f;

            #pragma unroll
            for (int kk = 0; kk < DH; kk += 8) {
                unsigned afr[2][4], bfr[2][2];
                #pragma unroll
                for (int mt = 0; mt < 2; mt++) {
                    int m0 = warpM * 32 + mt * 16 + (lane >> 2);
                    int k0 = kk + (lane & 3);
                    afr[mt][0] = Qu[(m0    ) * AQSTR + k0    ];
                    afr[mt][1] = Qu[(m0 + 8) * AQSTR + k0    ];
                    afr[mt][2] = Qu[(m0    ) * AQSTR + k0 + 4];
                    afr[mt][3] = Qu[(m0 + 8) * AQSTR + k0 + 4];
                }
                #pragma unroll
                for (int nt = 0; nt < 2; nt++) {
                    int n0 = warpN * 16 + nt * 8 + (lane >> 2);
                    int k0 = kk + (lane & 3);
                    bfr[nt][0] = Ku[n0 * AQSTR + k0    ];
                    bfr[nt][1] = Ku[n0 * AQSTR + k0 + 4];
                }
                #pragma unroll
                for (int mt = 0; mt < 2; mt++)
                    #pragma unroll
                    for (int nt = 0; nt < 2; nt++)
                        mma_tf32(sacc[mt][nt], afr[mt], bfr[nt]);
            }

            const bool diag = (kt == qt);
            #pragma unroll
            for (int mt = 0; mt < 2; mt++) {
                #pragma unroll
                for (int nt = 0; nt < 2; nt++) {
                    int r = warpM * 32 + mt * 16 + (lane >> 2);
                    int c = warpN * 16 + nt * 8 + (lane & 3) * 2;
                    float v0 = sacc[mt][nt][0], v1 = sacc[mt][nt][1];
                    float v2 = sacc[mt][nt][2], v3 = sacc[mt][nt][3];
                    if (diag) {
                        int qi0 = q0 + r, qi1 = q0 + r + 8;
                        int kj0 = k0g + c, kj1 = k0g + c + 1;
                        if (kj0 > qi0) v0 = -1e30f;
                        if (kj1 > qi0) v1 = -1e30f;
                        if (kj0 > qi1) v2 = -1e30f;
                        if (kj1 > qi1) v3 = -1e30f;
                    }
                    *(float2*)(sS + r * ASSTR + c)       = make_float2(v0, v1);
                    *(float2*)(sS + (r + 8) * ASSTR + c) = make_float2(v2, v3);
                }
            }
        }
        __syncthreads();

        // ---- Online softmax (scale applied here, fp32) ----
        {
            const int r = tid >> 2, sub = tid & 3;
            float* row = sS + r * ASSTR;
            float m_old = sMx[r];
            float mx = m_old;
            #pragma unroll
            for (int j = 0; j < 16; j++)
                mx = fmaxf(mx, row[sub + 4 * j] * scale);
            mx = fmaxf(mx, __shfl_xor_sync(0xFFFFFFFFu, mx, 1));
            mx = fmaxf(mx, __shfl_xor_sync(0xFFFFFFFFu, mx, 2));
            float sum = 0.0f;
            #pragma unroll
            for (int j = 0; j < 16; j++) {
                float p = __expf(row[sub + 4 * j] * scale - mx);
                float pr = rnd_tf32(p);
                row[sub + 4 * j] = pr;
                sum += pr;
            }
            sum += __shfl_xor_sync(0xFFFFFFFFu, sum, 1);
            sum += __shfl_xor_sync(0xFFFFFFFFu, sum, 2);
            if (sub == 0) {
                float alpha = __expf(m_old - mx);
                sAl[r] = alpha;
                sMx[r] = mx;
                sL[r]  = sL[r] * alpha + sum;
            }
        }
        __syncthreads();

        // ---- O = O*alpha + P @ V ----
        {
            const unsigned* Su = (const unsigned*)sS;
            const unsigned* Vu = (const unsigned*)(sV + stage * KV_STAGE_V);
            #pragma unroll
            for (int mt = 0; mt < 2; mt++) {
                int r0 = warpM * 32 + mt * 16 + (lane >> 2);
                float a0 = sAl[r0], a1 = sAl[r0 + 8];
                #pragma unroll
                for (int nt = 0; nt < 4; nt++) {
                    oacc[mt][nt][0] *= a0;
                    oacc[mt][nt][1] *= a0;
                    oacc[mt][nt][2] *= a1;
                    oacc[mt][nt][3] *= a1;
                }
            }
            #pragma unroll
            for (int kk = 0; kk < 64; kk += 8) {
                unsigned pfr[2][4], vfr[4][2];
                #pragma unroll
                for (int mt = 0; mt < 2; mt++) {
                    int m0 = warpM * 32 + mt * 16 + (lane >> 2);
                    int k0 = kk + (lane & 3);
                    pfr[mt][0] = Su[(m0    ) * ASSTR + k0    ];
                    pfr[mt][1] = Su[(m0 + 8) * ASSTR + k0    ];
                    pfr[mt][2] = Su[(m0    ) * ASSTR + k0 + 4];
                    pfr[mt][3] = Su[(m0 + 8) * ASSTR + k0 + 4];
                }
                #pragma unroll
                for (int nt = 0; nt < 4; nt++) {
                    int n0 = warpN * 32 + nt * 8 + (lane >> 2);
                    int k0 = kk + (lane & 3);
                    vfr[nt][0] = Vu[(k0    ) * AVSTR + n0];
                    vfr[nt][1] = Vu[(k0 + 4) * AVSTR + n0];
                }
                #pragma unroll
                for (int mt = 0; mt < 2; mt++)
                    #pragma unroll
                    for (int nt = 0; nt < 4; nt++)
                        mma_tf32(oacc[mt][nt], pfr[mt], vfr[nt]);
            }
        }
        __syncthreads();
    }

    // ---- Epilogue: normalize, tf32-round (feeds proj GEMM), write y ----
    #pragma unroll
    for (int mt = 0; mt < 2; mt++) {
        int r = warpM * 32 + mt * 16 + (lane >> 2);
        float inv0 = 1.0f / sL[r];
        float inv1 = 1.0f / sL[r + 8];
        #pragma unroll
        for (int nt = 0; nt < 4; nt++) {
            int c = warpN * 32 + nt * 8 + (lane & 3) * 2;
            float* y0 = y + ((size_t)(b * TT + q0 + r)) * EMB + h * DH + c;
            float* y1 = y + ((size_t)(b * TT + q0 + r + 8)) * EMB + h * DH + c;
            *(float2*)y0 = make_float2(rnd_tf32(oacc[mt][nt][0] * inv0),
                                       rnd_tf32(oacc[mt][nt][1] * inv0));
            *(float2*)y1 = make_float2(rnd_tf32(oacc[mt][nt][2] * inv1),
                                       rnd_tf32(oacc[mt][nt][3] * inv1));
        }
    }
}

// ---------------------------------------------------------------------------
// Launch
// ---------------------------------------------------------------------------
extern "C" void kernel_launch(void* const* d_in, const int* in_sizes, int n_in,
                              void* d_out, int out_size)
{
    const float* x      = (const float*)d_in[0];
    const float* W_attn = (const float*)d_in[1];
    const float* W_proj = (const float*)d_in[2];
    float* out = (float*)d_out;

    float *qkv, *y, *xr, *w1r, *w2r;
    cudaGetSymbolAddress((void**)&qkv, g_qkv);
    cudaGetSymbolAddress((void**)&y,   g_y);
    cudaGetSymbolAddress((void**)&xr,  g_xr);
    cudaGetSymbolAddress((void**)&w1r, g_w1r);
    cudaGetSymbolAddress((void**)&w2r, g_w2r);

    const int M = BB * TT;   // 4096

    // Prologue: tf32-round all GEMM operands once.
    {
        int n4;
        n4 = (M * EMB) / 4;
        round_copy4<<<(n4 + 255) / 256, 256>>>((const float4*)x, (float4*)xr, n4);
        n4 = (EMB * QKV3) / 4;
        round_copy4<<<(n4 + 255) / 256, 256>>>((const float4*)W_attn, (float4*)w1r, n4);
        n4 = (EMB * EMB) / 4;
        round_copy4<<<(n4 + 255) / 256, 256>>>((const float4*)W_proj, (float4*)w2r, n4);
    }

    const int gemmSmem = 2 * STAGE_FLOATS * (int)sizeof(float);  // 71680 B
    cudaFuncSetAttribute(gemm_tf32<true>,
                         cudaFuncAttributeMaxDynamicSharedMemorySize, gemmSmem);
    cudaFuncSetAttribute(gemm_tf32<false>,
                         cudaFuncAttributeMaxDynamicSharedMemorySize, gemmSmem);

    // 1) QKV projection (rounded output -> attention fragments are cvt-free)
    {
        dim3 grid(QKV3 / GBN, M / GBM);
        gemm_tf32<true><<<grid, 256, gemmSmem>>>(M, QKV3, EMB, xr, w1r, qkv);
    }

    // 2) Flash attention (tensor core)
    {
        const int attnSmem = (64 * AQSTR + 2 * KV_STAGE_K + 2 * KV_STAGE_V +
                              64 * ASSTR + 3 * 64) * (int)sizeof(float);
        cudaFuncSetAttribute(flash_attn_tc,
                             cudaFuncAttributeMaxDynamicSharedMemorySize, attnSmem);
        dim3 grid(TT / 64, NH, BB);
        flash_attn_tc<<<grid, 256, attnSmem>>>(qkv, y);
    }

    // 3) Output projection
    {
        dim3 grid(EMB / GBN, M / GBM);
        gemm_tf32<false><<<grid, 256, gemmSmem>>>(M, EMB, EMB, y, w2r, out);
    }
}

// round 11
// speedup vs baseline: 5.6649x; 1.4908x over previous
#include <cuda_runtime.h>
#include <cuda_fp16.h>
#include <math.h>
#include <stdint.h>

// Problem constants
#define BB   2
#define TT   2048
#define EMB  2048
#define NH   16
#define DH   128
#define QKV3 (3 * EMB)    // 6144

// Scratch — device globals (no cudaMalloc allowed).
__device__ float  g_qkv[BB * TT * QKV3];   // [B,T,3C] fp32, tf32-valued
__device__ __half g_yh [BB * TT * EMB];    // [B,T,C]  fp16 (attention output)
__device__ __half g_xh [BB * TT * EMB];    // fp16 x
__device__ __half g_w1h[QKV3 * EMB];       // W_attn^T [6144,2048] fp16
__device__ __half g_w2h[EMB * EMB];        // W_proj^T [2048,2048] fp16

// ---------------------------------------------------------------------------
// helpers
// ---------------------------------------------------------------------------
__device__ __forceinline__ unsigned f2tf32(float f) {
    unsigned r;
    asm volatile("cvt.rna.tf32.f32 %0, %1;" : "=r"(r) : "f"(f));
    return r;
}
__device__ __forceinline__ float rnd_tf32(float f) { return __uint_as_float(f2tf32(f)); }

__device__ __forceinline__ void mma_tf32(float* c, const unsigned* a, const unsigned* b) {
    asm volatile(
        "mma.sync.aligned.m16n8k8.row.col.f32.tf32.tf32.f32 "
        "{%0,%1,%2,%3}, {%4,%5,%6,%7}, {%8,%9}, {%0,%1,%2,%3};"
        : "+f"(c[0]), "+f"(c[1]), "+f"(c[2]), "+f"(c[3])
        : "r"(a[0]), "r"(a[1]), "r"(a[2]), "r"(a[3]),
          "r"(b[0]), "r"(b[1]));
}

__device__ __forceinline__ void mma_f16(float* c, const unsigned* a, const unsigned* b) {
    asm volatile(
        "mma.sync.aligned.m16n8k16.row.col.f32.f16.f16.f32 "
        "{%0,%1,%2,%3}, {%4,%5,%6,%7}, {%8,%9}, {%0,%1,%2,%3};"
        : "+f"(c[0]), "+f"(c[1]), "+f"(c[2]), "+f"(c[3])
        : "r"(a[0]), "r"(a[1]), "r"(a[2]), "r"(a[3]),
          "r"(b[0]), "r"(b[1]));
}

#define CP_ASYNC16(dst, src) \
    asm volatile("cp.async.cg.shared.global [%0], [%1], 16;\n" :: "r"(dst), "l"(src))
#define CP_COMMIT() asm volatile("cp.async.commit_group;\n" ::)
#define CP_WAIT(n)  asm volatile("cp.async.wait_group %0;\n" :: "n"(n))

// ---------------------------------------------------------------------------
// Prologue: fp16 conversion / transpose
// ---------------------------------------------------------------------------
__global__ void to_half4(const float4* __restrict__ src, __half2* __restrict__ dst, int n4)
{
    int i = blockIdx.x * blockDim.x + threadIdx.x;
    if (i < n4) {
        float4 v = src[i];
        dst[2 * i + 0] = __floats2half2_rn(v.x, v.y);
        dst[2 * i + 1] = __floats2half2_rn(v.z, v.w);
    }
}

// W[K][N] fp32 -> WT[N][K] fp16. block (32,8), grid (N/32, K/32).
__global__ void transpose_half(const float* __restrict__ W, __half* __restrict__ WT,
                               int K, int N)
{
    __shared__ float tile[32][33];
    int nBase = blockIdx.x * 32, kBase = blockIdx.y * 32;
    int tx = threadIdx.x, ty = threadIdx.y;
    #pragma unroll
    for (int i = ty; i < 32; i += 8)
        tile[i][tx] = W[(size_t)(kBase + i) * N + nBase + tx];
    __syncthreads();
    #pragma unroll
    for (int i = ty; i < 32; i += 8)
        WT[(size_t)(nBase + i) * K + kBase + tx] = __float2half_rn(tile[tx][i]);
}

// ---------------------------------------------------------------------------
// fp16 tensor-core GEMM: C[M,N] (fp32) = A[M,K] @ BT[N,K]^T, both fp16 K-major.
// BM=BN=128, BK=32, 256 threads (8 warps, 2x4 grid, warp tile 64x32),
// m16n8k16 mma, 3-stage cp.async pipeline.
// Smem rows: 32 halves = 16 words data + 4 pad = 20-word stride (conflict-free:
//   fragment addr mod 32 = 4*(lane>>2) + lane&3 pattern covers 32 banks).
// ROUND: tf32-round C on store (qkv must be tf32-valued for attention).
// ---------------------------------------------------------------------------
#define FBM 128
#define FBN 128
#define FBK 32
#define FSTR 20                       // 32-bit words per smem row
#define F_A_WORDS (FBM * FSTR)        // 2560 words per operand stage
#define F_STAGE_WORDS (2 * F_A_WORDS) // 5120 words = 20480 B
#define FNSTAGE 3
#define F_SMEM (FNSTAGE * F_STAGE_WORDS * 4)   // 61440 B

template<bool ROUND>
__global__ __launch_bounds__(256)
void gemm_f16(int M, int N, int K,
              const __half* __restrict__ A,
              const __half* __restrict__ BT,
              float* __restrict__ C)
{
    extern __shared__ uint32_t smw[];
    const unsigned sbase = (unsigned)__cvta_generic_to_shared(smw);

    const int tid  = threadIdx.x;
    const int lane = tid & 31;
    const int warp = tid >> 5;
    const int warpM = warp & 1;
    const int warpN = warp >> 1;
    const int mBase = warpM * 64;
    const int nBase = warpN * 32;

    const size_t rowOff = (size_t)blockIdx.y * FBM;
    const size_t colOff = (size_t)blockIdx.x * FBN;
    const int numTiles = K / FBK;

    // loader: each operand = 128 rows x 64 B = 512 granules; 2 per thread.
    auto load_tile = [&](int t, int s) {
        const __half* Ag = A  + rowOff * K + (size_t)t * FBK;
        const __half* Bg = BT + colOff * K + (size_t)t * FBK;
        unsigned sa = sbase + s * F_STAGE_WORDS * 4;
        unsigned sb = sa + F_A_WORDS * 4;
        #pragma unroll
        for (int i = 0; i < 2; i++) {
            int idx = tid + 256 * i;
            int r = idx >> 2, g = idx & 3;
            CP_ASYNC16(sa + r * 80 + g * 16, Ag + (size_t)r * K + g * 8);
            CP_ASYNC16(sb + r * 80 + g * 16, Bg + (size_t)r * K + g * 8);
        }
        CP_COMMIT();
    };

    float acc[4][4][4];
    #pragma unroll
    for (int i = 0; i < 4; i++)
        #pragma unroll
        for (int j = 0; j < 4; j++)
            #pragma unroll
            for (int r = 0; r < 4; r++) acc[i][j][r] = 0.0f;

    load_tile(0, 0);
    load_tile(1, 1);

    int s = 0;
    for (int t = 0; t < numTiles; t++) {
        if (t + 2 < numTiles) {
            int s2 = s + 2; if (s2 >= FNSTAGE) s2 -= FNSTAGE;
            load_tile(t + 2, s2);
            CP_WAIT(2);
        } else {
            CP_WAIT(0);
        }
        __syncthreads();

        const uint32_t* Au = smw + s * F_STAGE_WORDS;
        const uint32_t* Bu = Au + F_A_WORDS;

        #pragma unroll
        for (int ks = 0; ks < 2; ks++) {           // two k16 steps per tile
            const int kw = ks * 8;                 // word offset (16 halves)
            unsigned afr[4][4], bfr[4][2];
            #pragma unroll
            for (int mt = 0; mt < 4; mt++) {
                int m0 = mBase + mt * 16 + (lane >> 2);
                int w0 = m0 * FSTR + kw + (lane & 3);
                afr[mt][0] = Au[w0];
                afr[mt][1] = Au[w0 + 8 * FSTR];
                afr[mt][2] = Au[w0 + 4];
                afr[mt][3] = Au[w0 + 8 * FSTR + 4];
            }
            #pragma unroll
            for (int nt = 0; nt < 4; nt++) {
                int n0 = nBase + nt * 8 + (lane >> 2);
                int w0 = n0 * FSTR + kw + (lane & 3);
                bfr[nt][0] = Bu[w0];
                bfr[nt][1] = Bu[w0 + 4];
            }
            #pragma unroll
            for (int mt = 0; mt < 4; mt++)
                #pragma unroll
                for (int nt = 0; nt < 4; nt++)
                    mma_f16(acc[mt][nt], afr[mt], bfr[nt]);
        }
        __syncthreads();   // protect stage s before it is refilled
        if (++s == FNSTAGE) s = 0;
    }

    float* Cb = C + rowOff * N + colOff;
    #pragma unroll
    for (int mt = 0; mt < 4; mt++) {
        #pragma unroll
        for (int nt = 0; nt < 4; nt++) {
            int row = mBase + mt * 16 + (lane >> 2);
            int col = nBase + nt * 8 + (lane & 3) * 2;
            float v0 = acc[mt][nt][0], v1 = acc[mt][nt][1];
            float v2 = acc[mt][nt][2], v3 = acc[mt][nt][3];
            if (ROUND) {
                v0 = rnd_tf32(v0); v1 = rnd_tf32(v1);
                v2 = rnd_tf32(v2); v3 = rnd_tf32(v3);
            }
            *(float2*)(Cb + (size_t)row * N + col)       = make_float2(v0, v1);
            *(float2*)(Cb + (size_t)(row + 8) * N + col) = make_float2(v2, v3);
        }
    }
}

// ---------------------------------------------------------------------------
// Tensor-core flash attention (tf32 mma.sync, fp32 accum, causal).
// Mainloop identical to the R8 passing kernel (qkv tf32-valued fp32).
// Epilogue writes fp16 y for the fp16 projection GEMM.
// ---------------------------------------------------------------------------
#define AQSTR 132
#define AVSTR 136
#define ASSTR 68
#define KV_STAGE_K (64 * AQSTR)
#define KV_STAGE_V (64 * AVSTR)

__global__ __launch_bounds__(256)
void flash_attn_tc(const float* __restrict__ qkv, __half* __restrict__ yh)
{
    const int qt = blockIdx.x;
    const int h  = blockIdx.y;
    const int b  = blockIdx.z;
    const int q0 = qt * 64;
    const int tid  = threadIdx.x;
    const int lane = tid & 31;
    const int warp = tid >> 5;
    const int warpM = warp & 1;
    const int warpN = warp >> 1;

    extern __shared__ float sm[];
    float* sQ  = sm;
    float* sK  = sQ + 64 * AQSTR;
    float* sV  = sK + 2 * KV_STAGE_K;
    float* sS  = sV + 2 * KV_STAGE_V;
    float* sMx = sS + 64 * ASSTR;
    float* sL  = sMx + 64;
    float* sAl = sL + 64;

    const float scale = 0.08838834764831845f;

    {
        const float* qbase = qkv + ((size_t)(b * TT + q0)) * QKV3 + h * DH;
        #pragma unroll
        for (int i = 0; i < 8; i++) {
            int e = tid + 256 * i;
            int r = e >> 5, d4 = (e & 31) * 4;
            *(float4*)(sQ + r * AQSTR + d4) =
                *(const float4*)(qbase + (size_t)r * QKV3 + d4);
        }
    }
    if (tid < 64) { sMx[tid] = -1e30f; sL[tid] = 0.0f; }

    float oacc[2][4][4];
    #pragma unroll
    for (int mt = 0; mt < 2; mt++)
        #pragma unroll
        for (int nt = 0; nt < 4; nt++)
            #pragma unroll
            for (int r = 0; r < 4; r++) oacc[mt][nt][r] = 0.0f;

    auto issue_kv = [&](int kt, int stage) {
        const int k0 = kt * 64;
        const float* kbase = qkv + ((size_t)(b * TT + k0)) * QKV3 + EMB + h * DH;
        const float* vbase = qkv + ((size_t)(b * TT + k0)) * QKV3 + 2 * EMB + h * DH;
        unsigned sk = (unsigned)__cvta_generic_to_shared(sK + stage * KV_STAGE_K);
        unsigned sv = (unsigned)__cvta_generic_to_shared(sV + stage * KV_STAGE_V);
        #pragma unroll
        for (int i = 0; i < 8; i++) {
            int e = tid + 256 * i;
            int r = e >> 5, d4 = (e & 31) * 4;
            CP_ASYNC16(sk + (r * AQSTR + d4) * 4, kbase + (size_t)r * QKV3 + d4);
            CP_ASYNC16(sv + (r * AVSTR + d4) * 4, vbase + (size_t)r * QKV3 + d4);
        }
        CP_COMMIT();
    };

    issue_kv(0, 0);
    __syncthreads();

    for (int kt = 0; kt <= qt; kt++) {
        const int stage = kt & 1;
        const int k0g = kt * 64;

        if (kt + 1 <= qt) {
            issue_kv(kt + 1, (kt + 1) & 1);
            CP_WAIT(1);
        } else {
            CP_WAIT(0);
        }
        __syncthreads();

        // ---- S = Q @ K^T (unscaled) ----
        {
            const unsigned* Qu = (const unsigned*)sQ;
            const unsigned* Ku = (const unsigned*)(sK + stage * KV_STAGE_K);
            float sacc[2][2][4];
            #pragma unroll
            for (int mt = 0; mt < 2; mt++)
                #pragma unroll
                for (int nt = 0; nt < 2; nt++)
                    #pragma unroll
                    for (int r = 0; r < 4; r++) sacc[mt][nt][r] = 0.0f;

            #pragma unroll
            for (int kk = 0; kk < DH; kk += 8) {
                unsigned afr[2][4], bfr[2][2];
                #pragma unroll
                for (int mt = 0; mt < 2; mt++) {
                    int m0 = warpM * 32 + mt * 16 + (lane >> 2);
                    int k0 = kk + (lane & 3);
                    afr[mt][0] = Qu[(m0    ) * AQSTR + k0    ];
                    afr[mt][1] = Qu[(m0 + 8) * AQSTR + k0    ];
                    afr[mt][2] = Qu[(m0    ) * AQSTR + k0 + 4];
                    afr[mt][3] = Qu[(m0 + 8) * AQSTR + k0 + 4];
                }
                #pragma unroll
                for (int nt = 0; nt < 2; nt++) {
                    int n0 = warpN * 16 + nt * 8 + (lane >> 2);
                    int k0 = kk + (lane & 3);
                    bfr[nt][0] = Ku[n0 * AQSTR + k0    ];
                    bfr[nt][1] = Ku[n0 * AQSTR + k0 + 4];
                }
                #pragma unroll
                for (int mt = 0; mt < 2; mt++)
                    #pragma unroll
                    for (int nt = 0; nt < 2; nt++)
                        mma_tf32(sacc[mt][nt], afr[mt], bfr[nt]);
            }

            const bool diag = (kt == qt);
            #pragma unroll
            for (int mt = 0; mt < 2; mt++) {
                #pragma unroll
                for (int nt = 0; nt < 2; nt++) {
                    int r = warpM * 32 + mt * 16 + (lane >> 2);
                    int c = warpN * 16 + nt * 8 + (lane & 3) * 2;
                    float v0 = sacc[mt][nt][0], v1 = sacc[mt][nt][1];
                    float v2 = sacc[mt][nt][2], v3 = sacc[mt][nt][3];
                    if (diag) {
                        int qi0 = q0 + r, qi1 = q0 + r + 8;
                        int kj0 = k0g + c, kj1 = k0g + c + 1;
                        if (kj0 > qi0) v0 = -1e30f;
                        if (kj1 > qi0) v1 = -1e30f;
                        if (kj0 > qi1) v2 = -1e30f;
                        if (kj1 > qi1) v3 = -1e30f;
                    }
                    *(float2*)(sS + r * ASSTR + c)       = make_float2(v0, v1);
                    *(float2*)(sS + (r + 8) * ASSTR + c) = make_float2(v2, v3);
                }
            }
        }
        __syncthreads();

        // ---- Online softmax (scale applied here, fp32) ----
        {
            const int r = tid >> 2, sub = tid & 3;
            float* row = sS + r * ASSTR;
            float m_old = sMx[r];
            float mx = m_old;
            #pragma unroll
            for (int j = 0; j < 16; j++)
                mx = fmaxf(mx, row[sub + 4 * j] * scale);
            mx = fmaxf(mx, __shfl_xor_sync(0xFFFFFFFFu, mx, 1));
            mx = fmaxf(mx, __shfl_xor_sync(0xFFFFFFFFu, mx, 2));
            float sum = 0.0f;
            #pragma unroll
            for (int j = 0; j < 16; j++) {
                float p = __expf(row[sub + 4 * j] * scale - mx);
                float pr = rnd_tf32(p);
                row[sub + 4 * j] = pr;
                sum += pr;
            }
            sum += __shfl_xor_sync(0xFFFFFFFFu, sum, 1);
            sum += __shfl_xor_sync(0xFFFFFFFFu, sum, 2);
            if (sub == 0) {
                float alpha = __expf(m_old - mx);
                sAl[r] = alpha;
                sMx[r] = mx;
                sL[r]  = sL[r] * alpha + sum;
            }
        }
        __syncthreads();

        // ---- O = O*alpha + P @ V ----
        {
            const unsigned* Su = (const unsigned*)sS;
            const unsigned* Vu = (const unsigned*)(sV + stage * KV_STAGE_V);
            #pragma unroll
            for (int mt = 0; mt < 2; mt++) {
                int r0 = warpM * 32 + mt * 16 + (lane >> 2);
                float a0 = sAl[r0], a1 = sAl[r0 + 8];
                #pragma unroll
                for (int nt = 0; nt < 4; nt++) {
                    oacc[mt][nt][0] *= a0;
                    oacc[mt][nt][1] *= a0;
                    oacc[mt][nt][2] *= a1;
                    oacc[mt][nt][3] *= a1;
                }
            }
            #pragma unroll
            for (int kk = 0; kk < 64; kk += 8) {
                unsigned pfr[2][4], vfr[4][2];
                #pragma unroll
                for (int mt = 0; mt < 2; mt++) {
                    int m0 = warpM * 32 + mt * 16 + (lane >> 2);
                    int k0 = kk + (lane & 3);
                    pfr[mt][0] = Su[(m0    ) * ASSTR + k0    ];
                    pfr[mt][1] = Su[(m0 + 8) * ASSTR + k0    ];
                    pfr[mt][2] = Su[(m0    ) * ASSTR + k0 + 4];
                    pfr[mt][3] = Su[(m0 + 8) * ASSTR + k0 + 4];
                }
                #pragma unroll
                for (int nt = 0; nt < 4; nt++) {
                    int n0 = warpN * 32 + nt * 8 + (lane >> 2);
                    int k0 = kk + (lane & 3);
                    vfr[nt][0] = Vu[(k0    ) * AVSTR + n0];
                    vfr[nt][1] = Vu[(k0 + 4) * AVSTR + n0];
                }
                #pragma unroll
                for (int mt = 0; mt < 2; mt++)
                    #pragma unroll
                    for (int nt = 0; nt < 4; nt++)
                        mma_tf32(oacc[mt][nt], pfr[mt], vfr[nt]);
            }
        }
        __syncthreads();
    }

    // ---- Epilogue: normalize, write fp16 y (feeds fp16 proj GEMM) ----
    #pragma unroll
    for (int mt = 0; mt < 2; mt++) {
        int r = warpM * 32 + mt * 16 + (lane >> 2);
        float inv0 = 1.0f / sL[r];
        float inv1 = 1.0f / sL[r + 8];
        #pragma unroll
        for (int nt = 0; nt < 4; nt++) {
            int c = warpN * 32 + nt * 8 + (lane & 3) * 2;
            __half* y0 = yh + ((size_t)(b * TT + q0 + r)) * EMB + h * DH + c;
            __half* y1 = yh + ((size_t)(b * TT + q0 + r + 8)) * EMB + h * DH + c;
            *(__half2*)y0 = __floats2half2_rn(oacc[mt][nt][0] * inv0,
                                              oacc[mt][nt][1] * inv0);
            *(__half2*)y1 = __floats2half2_rn(oacc[mt][nt][2] * inv1,
                                              oacc[mt][nt][3] * inv1);
        }
    }
}

// ---------------------------------------------------------------------------
// Launch
// ---------------------------------------------------------------------------
extern "C" void kernel_launch(void* const* d_in, const int* in_sizes, int n_in,
                              void* d_out, int out_size)
{
    const float* x      = (const float*)d_in[0];
    const float* W_attn = (const float*)d_in[1];
    const float* W_proj = (const float*)d_in[2];
    float* out = (float*)d_out;

    float *qkv; __half *yh, *xh, *w1h, *w2h;
    cudaGetSymbolAddress((void**)&qkv, g_qkv);
    cudaGetSymbolAddress((void**)&yh,  g_yh);
    cudaGetSymbolAddress((void**)&xh,  g_xh);
    cudaGetSymbolAddress((void**)&w1h, g_w1h);
    cudaGetSymbolAddress((void**)&w2h, g_w2h);

    const int M = BB * TT;   // 4096

    // Prologue: fp16 x; fp16 transposed weights.
    {
        int n4 = (M * EMB) / 4;
        to_half4<<<(n4 + 255) / 256, 256>>>((const float4*)x, (__half2*)xh, n4);
        transpose_half<<<dim3(QKV3 / 32, EMB / 32), dim3(32, 8)>>>(W_attn, w1h, EMB, QKV3);
        transpose_half<<<dim3(EMB / 32, EMB / 32), dim3(32, 8)>>>(W_proj, w2h, EMB, EMB);
    }

    cudaFuncSetAttribute(gemm_f16<true>,
                         cudaFuncAttributeMaxDynamicSharedMemorySize, F_SMEM);
    cudaFuncSetAttribute(gemm_f16<false>,
                         cudaFuncAttributeMaxDynamicSharedMemorySize, F_SMEM);

    // 1) QKV projection (fp16 in, tf32-valued fp32 out)
    {
        dim3 grid(QKV3 / FBN, M / FBM);
        gemm_f16<true><<<grid, 256, F_SMEM>>>(M, QKV3, EMB, xh, w1h, qkv);
    }

    // 2) Flash attention (tf32 tensor core, unchanged mainloop)
    {
        const int attnSmem = (64 * AQSTR + 2 * KV_STAGE_K + 2 * KV_STAGE_V +
                              64 * ASSTR + 3 * 64) * (int)sizeof(float);
        cudaFuncSetAttribute(flash_attn_tc,
                             cudaFuncAttributeMaxDynamicSharedMemorySize, attnSmem);
        dim3 grid(TT / 64, NH, BB);
        flash_attn_tc<<<grid, 256, attnSmem>>>(qkv, yh);
    }

    // 3) Output projection (fp16 in, fp32 out)
    {
        dim3 grid(EMB / FBN, M / FBM);
        gemm_f16<false><<<grid, 256, F_SMEM>>>(M, EMB, EMB, yh, w2h, out);
    }
}

// round 14
// speedup vs baseline: 6.2699x; 1.1068x over previous
#include <cuda_runtime.h>
#include <cuda_fp16.h>
#include <math.h>
#include <stdint.h>

// Problem constants
#define BB   2
#define TT   2048
#define EMB  2048
#define NH   16
#define DH   128
#define QKV3 (3 * EMB)    // 6144
#define C2   (2 * EMB)    // 4096

// Scratch — device globals (no cudaMalloc allowed).
__device__ __half g_qk [BB * TT * C2];     // Q|K [B,T,2C] fp16
__device__ float  g_v  [BB * TT * EMB];    // V   [B,T,C]  fp32, tf32-valued
__device__ __half g_yh [BB * TT * EMB];    // attention output fp16
__device__ __half g_xh [BB * TT * EMB];    // fp16 x
__device__ __half g_w1h[QKV3 * EMB];       // W_attn^T [6144,2048] fp16
__device__ __half g_w2h[EMB * EMB];        // W_proj^T [2048,2048] fp16

// ---------------------------------------------------------------------------
// helpers
// ---------------------------------------------------------------------------
__device__ __forceinline__ unsigned f2tf32(float f) {
    unsigned r;
    asm volatile("cvt.rna.tf32.f32 %0, %1;" : "=r"(r) : "f"(f));
    return r;
}
__device__ __forceinline__ float rnd_tf32(float f) { return __uint_as_float(f2tf32(f)); }

__device__ __forceinline__ void mma_tf32(float* c, const unsigned* a, const unsigned* b) {
    asm volatile(
        "mma.sync.aligned.m16n8k8.row.col.f32.tf32.tf32.f32 "
        "{%0,%1,%2,%3}, {%4,%5,%6,%7}, {%8,%9}, {%0,%1,%2,%3};"
        : "+f"(c[0]), "+f"(c[1]), "+f"(c[2]), "+f"(c[3])
        : "r"(a[0]), "r"(a[1]), "r"(a[2]), "r"(a[3]),
          "r"(b[0]), "r"(b[1]));
}

__device__ __forceinline__ void mma_f16(float* c, const unsigned* a, const unsigned* b) {
    asm volatile(
        "mma.sync.aligned.m16n8k16.row.col.f32.f16.f16.f32 "
        "{%0,%1,%2,%3}, {%4,%5,%6,%7}, {%8,%9}, {%0,%1,%2,%3};"
        : "+f"(c[0]), "+f"(c[1]), "+f"(c[2]), "+f"(c[3])
        : "r"(a[0]), "r"(a[1]), "r"(a[2]), "r"(a[3]),
          "r"(b[0]), "r"(b[1]));
}

#define CP_ASYNC16(dst, src) \
    asm volatile("cp.async.cg.shared.global [%0], [%1], 16;\n" :: "r"(dst), "l"(src))
#define CP_COMMIT() asm volatile("cp.async.commit_group;\n" ::)
#define CP_WAIT(n)  asm volatile("cp.async.wait_group %0;\n" :: "n"(n))

// ---------------------------------------------------------------------------
// Prologue: fp16 conversion / transpose
// ---------------------------------------------------------------------------
__global__ void to_half4(const float4* __restrict__ src, __half2* __restrict__ dst, int n4)
{
    int i = blockIdx.x * blockDim.x + threadIdx.x;
    if (i < n4) {
        float4 v = src[i];
        dst[2 * i + 0] = __floats2half2_rn(v.x, v.y);
        dst[2 * i + 1] = __floats2half2_rn(v.z, v.w);
    }
}

__global__ void transpose_half(const float* __restrict__ W, __half* __restrict__ WT,
                               int K, int N)
{
    __shared__ float tile[32][33];
    int nBase = blockIdx.x * 32, kBase = blockIdx.y * 32;
    int tx = threadIdx.x, ty = threadIdx.y;
    #pragma unroll
    for (int i = ty; i < 32; i += 8)
        tile[i][tx] = W[(size_t)(kBase + i) * N + nBase + tx];
    __syncthreads();
    #pragma unroll
    for (int i = ty; i < 32; i += 8)
        WT[(size_t)(nBase + i) * K + kBase + tx] = __float2half_rn(tile[tx][i]);
}

// ---------------------------------------------------------------------------
// fp16 tensor-core GEMM (mainloop identical to R11 passing kernel).
// MODE 0: C = Cf fp32 (proj output, no rounding).
// MODE 1: split qkv epilogue — colOff <  2C: fp16 into Cqk [M,2C]
//                              colOff >= 2C: tf32-rounded fp32 into Cv [M,C]
// ---------------------------------------------------------------------------
#define FBM 128
#define FBN 128
#define FBK 32
#define FSTR 20
#define F_A_WORDS (FBM * FSTR)
#define F_STAGE_WORDS (2 * F_A_WORDS)
#define FNSTAGE 3
#define F_SMEM (FNSTAGE * F_STAGE_WORDS * 4)

template<int MODE>
__global__ __launch_bounds__(256)
void gemm_f16(int M, int N, int K,
              const __half* __restrict__ A,
              const __half* __restrict__ BT,
              float* __restrict__ Cf,
              __half* __restrict__ Cqk,
              float* __restrict__ Cv)
{
    extern __shared__ uint32_t smw[];
    const unsigned sbase = (unsigned)__cvta_generic_to_shared(smw);

    const int tid  = threadIdx.x;
    const int lane = tid & 31;
    const int warp = tid >> 5;
    const int warpM = warp & 1;
    const int warpN = warp >> 1;
    const int mBase = warpM * 64;
    const int nBase = warpN * 32;

    const size_t rowOff = (size_t)blockIdx.y * FBM;
    const size_t colOff = (size_t)blockIdx.x * FBN;
    const int numTiles = K / FBK;

    auto load_tile = [&](int t, int s) {
        const __half* Ag = A  + rowOff * K + (size_t)t * FBK;
        const __half* Bg = BT + colOff * K + (size_t)t * FBK;
        unsigned sa = sbase + s * F_STAGE_WORDS * 4;
        unsigned sb = sa + F_A_WORDS * 4;
        #pragma unroll
        for (int i = 0; i < 2; i++) {
            int idx = tid + 256 * i;
            int r = idx >> 2, g = idx & 3;
            CP_ASYNC16(sa + r * 80 + g * 16, Ag + (size_t)r * K + g * 8);
            CP_ASYNC16(sb + r * 80 + g * 16, Bg + (size_t)r * K + g * 8);
        }
        CP_COMMIT();
    };

    float acc[4][4][4];
    #pragma unroll
    for (int i = 0; i < 4; i++)
        #pragma unroll
        for (int j = 0; j < 4; j++)
            #pragma unroll
            for (int r = 0; r < 4; r++) acc[i][j][r] = 0.0f;

    load_tile(0, 0);
    load_tile(1, 1);

    int s = 0;
    for (int t = 0; t < numTiles; t++) {
        if (t + 2 < numTiles) {
            int s2 = s + 2; if (s2 >= FNSTAGE) s2 -= FNSTAGE;
            load_tile(t + 2, s2);
            CP_WAIT(2);
        } else {
            CP_WAIT(0);
        }
        __syncthreads();

        const uint32_t* Au = smw + s * F_STAGE_WORDS;
        const uint32_t* Bu = Au + F_A_WORDS;

        #pragma unroll
        for (int ks = 0; ks < 2; ks++) {
            const int kw = ks * 8;
            unsigned afr[4][4], bfr[4][2];
            #pragma unroll
            for (int mt = 0; mt < 4; mt++) {
                int m0 = mBase + mt * 16 + (lane >> 2);
                int w0 = m0 * FSTR + kw + (lane & 3);
                afr[mt][0] = Au[w0];
                afr[mt][1] = Au[w0 + 8 * FSTR];
                afr[mt][2] = Au[w0 + 4];
                afr[mt][3] = Au[w0 + 8 * FSTR + 4];
            }
            #pragma unroll
            for (int nt = 0; nt < 4; nt++) {
                int n0 = nBase + nt * 8 + (lane >> 2);
                int w0 = n0 * FSTR + kw + (lane & 3);
                bfr[nt][0] = Bu[w0];
                bfr[nt][1] = Bu[w0 + 4];
            }
            #pragma unroll
            for (int mt = 0; mt < 4; mt++)
                #pragma unroll
                for (int nt = 0; nt < 4; nt++)
                    mma_f16(acc[mt][nt], afr[mt], bfr[nt]);
        }
        __syncthreads();
        if (++s == FNSTAGE) s = 0;
    }

    if (MODE == 0) {
        float* Cb = Cf + rowOff * N + colOff;
        #pragma unroll
        for (int mt = 0; mt < 4; mt++) {
            #pragma unroll
            for (int nt = 0; nt < 4; nt++) {
                int row = mBase + mt * 16 + (lane >> 2);
                int col = nBase + nt * 8 + (lane & 3) * 2;
                *(float2*)(Cb + (size_t)row * N + col) =
                    make_float2(acc[mt][nt][0], acc[mt][nt][1]);
                *(float2*)(Cb + (size_t)(row + 8) * N + col) =
                    make_float2(acc[mt][nt][2], acc[mt][nt][3]);
            }
        }
    } else if (colOff < (size_t)C2) {
        // Q|K columns -> fp16 buffer [M, 2C]
        __half* Cb = Cqk + rowOff * C2 + colOff;
        #pragma unroll
        for (int mt = 0; mt < 4; mt++) {
            #pragma unroll
            for (int nt = 0; nt < 4; nt++) {
                int row = mBase + mt * 16 + (lane >> 2);
                int col = nBase + nt * 8 + (lane & 3) * 2;
                *(__half2*)(Cb + (size_t)row * C2 + col) =
                    __floats2half2_rn(acc[mt][nt][0], acc[mt][nt][1]);
                *(__half2*)(Cb + (size_t)(row + 8) * C2 + col) =
                    __floats2half2_rn(acc[mt][nt][2], acc[mt][nt][3]);
            }
        }
    } else {
        // V columns -> tf32-valued fp32 buffer [M, C]
        float* Cb = Cv + rowOff * EMB + (colOff - C2);
        #pragma unroll
        for (int mt = 0; mt < 4; mt++) {
            #pragma unroll
            for (int nt = 0; nt < 4; nt++) {
                int row = mBase + mt * 16 + (lane >> 2);
                int col = nBase + nt * 8 + (lane & 3) * 2;
                *(float2*)(Cb + (size_t)row * EMB + col) =
                    make_float2(rnd_tf32(acc[mt][nt][0]), rnd_tf32(acc[mt][nt][1]));
                *(float2*)(Cb + (size_t)(row + 8) * EMB + col) =
                    make_float2(rnd_tf32(acc[mt][nt][2]), rnd_tf32(acc[mt][nt][3]));
            }
        }
    }
}

// ---------------------------------------------------------------------------
// Flash attention: fp16 S-phase (m16n8k16), fp32 softmax, tf32 PV.
// Q/K fp16 K-major tiles (word stride 68); V fp32 (stride 136); sS fp32 (68).
// ---------------------------------------------------------------------------
#define QKW 68                         // 32-bit words per Q/K row (64 data + 4 pad)
#define AVSTR 136
#define ASSTR 68
#define QK_TILE_W (64 * QKW)           // words per Q or K tile
#define V_STAGE (64 * AVSTR)           // floats per V stage

__global__ __launch_bounds__(256)
void flash_attn_tc(const __half* __restrict__ qk, const float* __restrict__ v,
                   __half* __restrict__ yh)
{
    const int qt = blockIdx.x;
    const int h  = blockIdx.y;
    const int b  = blockIdx.z;
    const int q0 = qt * 64;
    const int tid  = threadIdx.x;
    const int lane = tid & 31;
    const int warp = tid >> 5;
    const int warpM = warp & 1;
    const int warpN = warp >> 1;

    extern __shared__ uint32_t smw[];
    uint32_t* sQw = smw;                               // Q fp16 tile
    uint32_t* sKw = sQw + QK_TILE_W;                   // 2 stages K fp16
    float*    sV  = (float*)(sKw + 2 * QK_TILE_W);     // 2 stages V fp32
    float*    sS  = sV + 2 * V_STAGE;                  // scores fp32
    float*    sMx = sS + 64 * ASSTR;
    float*    sL  = sMx + 64;
    float*    sAl = sL + 64;

    const float scale = 0.08838834764831845f;

    // ---- Load Q tile (fp16, 64 rows x 128 halves) ----
    {
        const __half* qbase = qk + ((size_t)(b * TT + q0)) * C2 + h * DH;
        #pragma unroll
        for (int i = 0; i < 4; i++) {
            int idx = tid + 256 * i;          // 0..1023
            int r = idx >> 4, g = idx & 15;   // row, 16B granule
            *(uint4*)(sQw + r * QKW + g * 4) =
                *(const uint4*)(qbase + (size_t)r * C2 + g * 8);
        }
    }
    if (tid < 64) { sMx[tid] = -1e30f; sL[tid] = 0.0f; }

    float oacc[2][4][4];
    #pragma unroll
    for (int mt = 0; mt < 2; mt++)
        #pragma unroll
        for (int nt = 0; nt < 4; nt++)
            #pragma unroll
            for (int r = 0; r < 4; r++) oacc[mt][nt][r] = 0.0f;

    // ---- K (fp16) + V (fp32) tile loaders ----
    auto issue_kv = [&](int kt, int stage) {
        const int k0 = kt * 64;
        const __half* kbase = qk + ((size_t)(b * TT + k0)) * C2 + EMB + h * DH;
        const float*  vbase = v  + ((size_t)(b * TT + k0)) * EMB + h * DH;
        unsigned sk = (unsigned)__cvta_generic_to_shared(sKw + stage * QK_TILE_W);
        unsigned sv = (unsigned)__cvta_generic_to_shared(sV + stage * V_STAGE);
        #pragma unroll
        for (int i = 0; i < 4; i++) {                    // K: 1024 granules
            int idx = tid + 256 * i;
            int r = idx >> 4, g = idx & 15;
            CP_ASYNC16(sk + (r * QKW + g * 4) * 4, kbase + (size_t)r * C2 + g * 8);
        }
        #pragma unroll
        for (int i = 0; i < 8; i++) {                    // V: 2048 granules
            int idx = tid + 256 * i;
            int r = idx >> 5, g = idx & 31;
            CP_ASYNC16(sv + (r * AVSTR + g * 4) * 4, vbase + (size_t)r * EMB + g * 4);
        }
        CP_COMMIT();
    };

    issue_kv(0, 0);
    __syncthreads();

    for (int kt = 0; kt <= qt; kt++) {
        const int stage = kt & 1;
        const int k0g = kt * 64;

        if (kt + 1 <= qt) {
            issue_kv(kt + 1, (kt + 1) & 1);
            CP_WAIT(1);
        } else {
            CP_WAIT(0);
        }
        __syncthreads();

        // ---- S = Q @ K^T (fp16 m16n8k16, 8 k-steps) ----
        {
            const uint32_t* Ku = sKw + stage * QK_TILE_W;
            float sacc[2][2][4];
            #pragma unroll
            for (int mt = 0; mt < 2; mt++)
                #pragma unroll
                for (int nt = 0; nt < 2; nt++)
                    #pragma unroll
                    for (int r = 0; r < 4; r++) sacc[mt][nt][r] = 0.0f;

            #pragma unroll
            for (int ks = 0; ks < 8; ks++) {
                const int kw = ks * 8;        // 16 halves = 8 words per step
                unsigned afr[2][4], bfr[2][2];
                #pragma unroll
                for (int mt = 0; mt < 2; mt++) {
                    int m0 = warpM * 32 + mt * 16 + (lane >> 2);
                    int w0 = m0 * QKW + kw + (lane & 3);
                    afr[mt][0] = sQw[w0];
                    afr[mt][1] = sQw[w0 + 8 * QKW];
                    afr[mt][2] = sQw[w0 + 4];
                    afr[mt][3] = sQw[w0 + 8 * QKW + 4];
                }
                #pragma unroll
                for (int nt = 0; nt < 2; nt++) {
                    int n0 = warpN * 16 + nt * 8 + (lane >> 2);
                    int w0 = n0 * QKW + kw + (lane & 3);
                    bfr[nt][0] = Ku[w0];
                    bfr[nt][1] = Ku[w0 + 4];
                }
                #pragma unroll
                for (int mt = 0; mt < 2; mt++)
                    #pragma unroll
                    for (int nt = 0; nt < 2; nt++)
                        mma_f16(sacc[mt][nt], afr[mt], bfr[nt]);
            }

            const bool diag = (kt == qt);
            #pragma unroll
            for (int mt = 0; mt < 2; mt++) {
                #pragma unroll
                for (int nt = 0; nt < 2; nt++) {
                    int r = warpM * 32 + mt * 16 + (lane >> 2);
                    int c = warpN * 16 + nt * 8 + (lane & 3) * 2;
                    float v0 = sacc[mt][nt][0], v1 = sacc[mt][nt][1];
                    float v2 = sacc[mt][nt][2], v3 = sacc[mt][nt][3];
                    if (diag) {
                        int qi0 = q0 + r, qi1 = q0 + r + 8;
                        int kj0 = k0g + c, kj1 = k0g + c + 1;
                        if (kj0 > qi0) v0 = -1e30f;
                        if (kj1 > qi0) v1 = -1e30f;
                        if (kj0 > qi1) v2 = -1e30f;
                        if (kj1 > qi1) v3 = -1e30f;
                    }
                    *(float2*)(sS + r * ASSTR + c)       = make_float2(v0, v1);
                    *(float2*)(sS + (r + 8) * ASSTR + c) = make_float2(v2, v3);
                }
            }
        }
        __syncthreads();

        // ---- Online softmax (fp32; 1/sqrt(d) applied here) ----
        {
            const int r = tid >> 2, sub = tid & 3;
            float* row = sS + r * ASSTR;
            float m_old = sMx[r];
            float mx = m_old;
            #pragma unroll
            for (int j = 0; j < 16; j++)
                mx = fmaxf(mx, row[sub + 4 * j] * scale);
            mx = fmaxf(mx, __shfl_xor_sync(0xFFFFFFFFu, mx, 1));
            mx = fmaxf(mx, __shfl_xor_sync(0xFFFFFFFFu, mx, 2));
            float sum = 0.0f;
            #pragma unroll
            for (int j = 0; j < 16; j++) {
                float p = __expf(row[sub + 4 * j] * scale - mx);
                float pr = rnd_tf32(p);
                row[sub + 4 * j] = pr;
                sum += pr;
            }
            sum += __shfl_xor_sync(0xFFFFFFFFu, sum, 1);
            sum += __shfl_xor_sync(0xFFFFFFFFu, sum, 2);
            if (sub == 0) {
                float alpha = __expf(m_old - mx);
                sAl[r] = alpha;
                sMx[r] = mx;
                sL[r]  = sL[r] * alpha + sum;
            }
        }
        __syncthreads();

        // ---- O = O*alpha + P @ V (tf32, unchanged) ----
        {
            const unsigned* Su = (const unsigned*)sS;
            const unsigned* Vu = (const unsigned*)(sV + stage * V_STAGE);
            #pragma unroll
            for (int mt = 0; mt < 2; mt++) {
                int r0 = warpM * 32 + mt * 16 + (lane >> 2);
                float a0 = sAl[r0], a1 = sAl[r0 + 8];
                #pragma unroll
                for (int nt = 0; nt < 4; nt++) {
                    oacc[mt][nt][0] *= a0;
                    oacc[mt][nt][1] *= a0;
                    oacc[mt][nt][2] *= a1;
                    oacc[mt][nt][3] *= a1;
                }
            }
            #pragma unroll
            for (int kk = 0; kk < 64; kk += 8) {
                unsigned pfr[2][4], vfr[4][2];
                #pragma unroll
                for (int mt = 0; mt < 2; mt++) {
                    int m0 = warpM * 32 + mt * 16 + (lane >> 2);
                    int k0 = kk + (lane & 3);
                    pfr[mt][0] = Su[(m0    ) * ASSTR + k0    ];
                    pfr[mt][1] = Su[(m0 + 8) * ASSTR + k0    ];
                    pfr[mt][2] = Su[(m0    ) * ASSTR + k0 + 4];
                    pfr[mt][3] = Su[(m0 + 8) * ASSTR + k0 + 4];
                }
                #pragma unroll
                for (int nt = 0; nt < 4; nt++) {
                    int n0 = warpN * 32 + nt * 8 + (lane >> 2);
                    int k0 = kk + (lane & 3);
                    vfr[nt][0] = Vu[(k0    ) * AVSTR + n0];
                    vfr[nt][1] = Vu[(k0 + 4) * AVSTR + n0];
                }
                #pragma unroll
                for (int mt = 0; mt < 2; mt++)
                    #pragma unroll
                    for (int nt = 0; nt < 4; nt++)
                        mma_tf32(oacc[mt][nt], pfr[mt], vfr[nt]);
            }
        }
        __syncthreads();
    }

    // ---- Epilogue: normalize, write fp16 y ----
    #pragma unroll
    for (int mt = 0; mt < 2; mt++) {
        int r = warpM * 32 + mt * 16 + (lane >> 2);
        float inv0 = 1.0f / sL[r];
        float inv1 = 1.0f / sL[r + 8];
        #pragma unroll
        for (int nt = 0; nt < 4; nt++) {
            int c = warpN * 32 + nt * 8 + (lane & 3) * 2;
            __half* y0 = yh + ((size_t)(b * TT + q0 + r)) * EMB + h * DH + c;
            __half* y1 = yh + ((size_t)(b * TT + q0 + r + 8)) * EMB + h * DH + c;
            *(__half2*)y0 = __floats2half2_rn(oacc[mt][nt][0] * inv0,
                                              oacc[mt][nt][1] * inv0);
            *(__half2*)y1 = __floats2half2_rn(oacc[mt][nt][2] * inv1,
                                              oacc[mt][nt][3] * inv1);
        }
    }
}

#define ATTN_SMEM ((3 * QK_TILE_W + 2 * V_STAGE + 64 * ASSTR + 3 * 64) * 4)

// ---------------------------------------------------------------------------
// Launch
// ---------------------------------------------------------------------------
extern "C" void kernel_launch(void* const* d_in, const int* in_sizes, int n_in,
                              void* d_out, int out_size)
{
    const float* x      = (const float*)d_in[0];
    const float* W_attn = (const float*)d_in[1];
    const float* W_proj = (const float*)d_in[2];
    float* out = (float*)d_out;

    __half *qkh, *yh, *xh, *w1h, *w2h; float *vf;
    cudaGetSymbolAddress((void**)&qkh, g_qk);
    cudaGetSymbolAddress((void**)&vf,  g_v);
    cudaGetSymbolAddress((void**)&yh,  g_yh);
    cudaGetSymbolAddress((void**)&xh,  g_xh);
    cudaGetSymbolAddress((void**)&w1h, g_w1h);
    cudaGetSymbolAddress((void**)&w2h, g_w2h);

    const int M = BB * TT;   // 4096

    // Prologue: fp16 x; fp16 transposed weights.
    {
        int n4 = (M * EMB) / 4;
        to_half4<<<(n4 + 255) / 256, 256>>>((const float4*)x, (__half2*)xh, n4);
        transpose_half<<<dim3(QKV3 / 32, EMB / 32), dim3(32, 8)>>>(W_attn, w1h, EMB, QKV3);
        transpose_half<<<dim3(EMB / 32, EMB / 32), dim3(32, 8)>>>(W_proj, w2h, EMB, EMB);
    }

    cudaFuncSetAttribute(gemm_f16<0>,
                         cudaFuncAttributeMaxDynamicSharedMemorySize, F_SMEM);
    cudaFuncSetAttribute(gemm_f16<1>,
                         cudaFuncAttributeMaxDynamicSharedMemorySize, F_SMEM);

    // 1) QKV projection -> split Q|K (fp16) / V (tf32-valued fp32)
    {
        dim3 grid(QKV3 / FBN, M / FBM);
        gemm_f16<1><<<grid, 256, F_SMEM>>>(M, QKV3, EMB, xh, w1h,
                                           (float*)nullptr, qkh, vf);
    }

    // 2) Flash attention (fp16 S-phase, tf32 PV)
    {
        cudaFuncSetAttribute(flash_attn_tc,
                             cudaFuncAttributeMaxDynamicSharedMemorySize, ATTN_SMEM);
        dim3 grid(TT / 64, NH, BB);
        flash_attn_tc<<<grid, 256, ATTN_SMEM>>>(qkh, vf, yh);
    }

    // 3) Output projection (fp16 in, fp32 out)
    {
        dim3 grid(EMB / FBN, M / FBM);
        gemm_f16<0><<<grid, 256, F_SMEM>>>(M, EMB, EMB, yh, w2h,
                                           out, (__half*)nullptr, (float*)nullptr);
    }
}